// round 1
// baseline (speedup 1.0000x reference)
#include <cuda_runtime.h>
#include <cuda_bf16.h>
#include <cstddef>

// Problem constants
constexpr int Bb  = 64;
constexpr int Nn  = 197;
constexpr int Cc  = 768;
constexpr int Hh  = 12;
constexpr int Dd  = 64;
constexpr int M_TOT = Bb * Nn;        // 12608
constexpr int PLD  = 208;             // padded row stride for P (multiple of 16 floats)

// Scratch (device globals; allocation-free per harness rules)
__device__ float g_q[(size_t)Bb * Hh * Nn * Dd];       // [B,H,N,D], pre-scaled
__device__ float g_k[(size_t)Bb * Hh * Nn * Dd];
__device__ float g_v[(size_t)Bb * Hh * Nn * Dd];
__device__ float g_p[(size_t)Bb * Hh * Nn * PLD];      // [BH, N, PLD] scores/probs
__device__ float g_rpb[(size_t)Hh * Nn * Nn];          // [H, N, N]
__device__ float g_o[(size_t)Bb * Nn * Cc];            // [B, N, C] attn output

// ---------------------------------------------------------------------------
// Kernel 1: relative position bias gather  rpb[h][i][j] = rel_table[idx(i,j)][h]
// ---------------------------------------------------------------------------
__global__ void rpb_kernel(const float* __restrict__ rel_table) {
    int tid = blockIdx.x * blockDim.x + threadIdx.x;
    const int total = Hh * Nn * Nn;
    if (tid >= total) return;
    int h = tid / (Nn * Nn);
    int r = tid % (Nn * Nn);
    int i = r / Nn, j = r % Nn;
    int idx;
    if (i == 0 && j == 0)      idx = 731;   // nrd-1
    else if (i == 0)           idx = 729;   // nrd-3
    else if (j == 0)           idx = 730;   // nrd-2
    else {
        int a = i - 1, b = j - 1;
        int d0 = (a / 14 - b / 14) + 13;
        int d1 = (a % 14 - b % 14) + 13;
        idx = d0 * 27 + d1;
    }
    g_rpb[tid] = rel_table[idx * Hh + h];
}

// ---------------------------------------------------------------------------
// Kernels 2 & 6: 128x128x8 double-buffered fp32 SGEMM, C = A @ W^T (+bias)
// EPI==0: A = x (12608x768), W = qkv_w (2304x768), scatter into g_q/g_k/g_v
// EPI==1: A = g_o (12608x768), W = proj_w (768x768), out = A@W^T + proj_b
// ---------------------------------------------------------------------------
template <int EPI>
__global__ __launch_bounds__(256) void sgemm_kernel(
    const float* __restrict__ Ain, const float* __restrict__ W,
    const float* __restrict__ b0, const float* __restrict__ b1,
    const float* __restrict__ b2, float* __restrict__ out)
{
    constexpr int K = 768, BM = 128, BN = 128, BK = 8;
    __shared__ float As[2][BK][BM];
    __shared__ float Bs[2][BK][BN];

    const float* A = (EPI == 0) ? Ain : (const float*)g_o;
    const int tid  = threadIdx.x;
    const int bm   = blockIdx.y * BM;
    const int bn   = blockIdx.x * BN;

    const int lrow = tid >> 1;          // 0..127
    const int lk   = (tid & 1) * 4;     // 0 or 4
    const int arow = bm + lrow;
    const bool aval = arow < M_TOT;
    const float* Ap = A + (size_t)arow * K + lk;
    const float* Wp = W + (size_t)(bn + lrow) * K + lk;

    float acc[8][8];
#pragma unroll
    for (int i = 0; i < 8; i++)
#pragma unroll
        for (int j = 0; j < 8; j++) acc[i][j] = 0.f;

    float4 a4 = aval ? *(const float4*)Ap : make_float4(0, 0, 0, 0);
    float4 b4 = *(const float4*)Wp;
    As[0][lk + 0][lrow] = a4.x; As[0][lk + 1][lrow] = a4.y;
    As[0][lk + 2][lrow] = a4.z; As[0][lk + 3][lrow] = a4.w;
    Bs[0][lk + 0][lrow] = b4.x; Bs[0][lk + 1][lrow] = b4.y;
    Bs[0][lk + 2][lrow] = b4.z; Bs[0][lk + 3][lrow] = b4.w;
    __syncthreads();

    const int tx = (tid & 15) * 8;
    const int ty = (tid >> 4) * 8;
    int buf = 0;
    for (int k0 = BK; k0 <= K; k0 += BK) {
        if (k0 < K) {
            a4 = aval ? *(const float4*)(Ap + k0) : make_float4(0, 0, 0, 0);
            b4 = *(const float4*)(Wp + k0);
        }
#pragma unroll
        for (int kk = 0; kk < BK; kk++) {
            float ar[8], br[8];
#pragma unroll
            for (int i = 0; i < 8; i++) ar[i] = As[buf][kk][ty + i];
#pragma unroll
            for (int j = 0; j < 8; j++) br[j] = Bs[buf][kk][tx + j];
#pragma unroll
            for (int i = 0; i < 8; i++)
#pragma unroll
                for (int j = 0; j < 8; j++)
                    acc[i][j] = fmaf(ar[i], br[j], acc[i][j]);
        }
        if (k0 < K) {
            int nb = buf ^ 1;
            As[nb][lk + 0][lrow] = a4.x; As[nb][lk + 1][lrow] = a4.y;
            As[nb][lk + 2][lrow] = a4.z; As[nb][lk + 3][lrow] = a4.w;
            Bs[nb][lk + 0][lrow] = b4.x; Bs[nb][lk + 1][lrow] = b4.y;
            Bs[nb][lk + 2][lrow] = b4.z; Bs[nb][lk + 3][lrow] = b4.w;
            __syncthreads();
            buf = nb;
        }
    }

    // Epilogue
#pragma unroll
    for (int i = 0; i < 8; i++) {
        int row = bm + ty + i;
        if (row >= M_TOT) continue;
        int bIdx = row / Nn, n = row % Nn;
#pragma unroll
        for (int j = 0; j < 8; j++) {
            int c = bn + tx + j;
            float v = acc[i][j];
            if (EPI == 0) {
                int which = c / Cc;
                int cc = c % Cc;
                int h = cc >> 6, d = cc & 63;
                size_t off = (((size_t)bIdx * Hh + h) * Nn + n) * Dd + d;
                if (which == 0)      g_q[off] = (v + b0[cc]) * 0.125f; // scale=D^-0.5
                else if (which == 1) g_k[off] = v + b1[cc];
                else                 g_v[off] = v + b2[cc];
            } else {
                out[(size_t)row * Cc + c] = v + b0[c];
            }
        }
    }
}

// ---------------------------------------------------------------------------
// Kernel 3: scores  S[bh] = q[bh] @ k[bh]^T + rpb[h], stored to g_p (PLD stride)
// 64x64 tiles, K=64 fully resident in smem
// ---------------------------------------------------------------------------
__global__ __launch_bounds__(256) void scores_kernel() {
    __shared__ float Qs[64][65];
    __shared__ float Ks[64][65];
    const int bh = blockIdx.z;
    const int h  = bh % Hh;
    const int m0 = blockIdx.y * 64;
    const int n0 = blockIdx.x * 64;
    const int tid = threadIdx.x;
    const float* qb = g_q + (size_t)bh * Nn * Dd;
    const float* kb = g_k + (size_t)bh * Nn * Dd;

    {
        int r  = tid >> 2;           // 0..63
        int c0 = (tid & 3) * 16;     // 0,16,32,48
        int m = m0 + r, n = n0 + r;
#pragma unroll
        for (int ii = 0; ii < 4; ii++) {
            float4 v = (m < Nn) ? *(const float4*)(qb + (size_t)m * Dd + c0 + ii * 4)
                                : make_float4(0, 0, 0, 0);
            Qs[r][c0 + ii * 4 + 0] = v.x; Qs[r][c0 + ii * 4 + 1] = v.y;
            Qs[r][c0 + ii * 4 + 2] = v.z; Qs[r][c0 + ii * 4 + 3] = v.w;
            float4 w = (n < Nn) ? *(const float4*)(kb + (size_t)n * Dd + c0 + ii * 4)
                                : make_float4(0, 0, 0, 0);
            Ks[r][c0 + ii * 4 + 0] = w.x; Ks[r][c0 + ii * 4 + 1] = w.y;
            Ks[r][c0 + ii * 4 + 2] = w.z; Ks[r][c0 + ii * 4 + 3] = w.w;
        }
    }
    __syncthreads();

    const int tx = (tid & 15) * 4;
    const int ty = (tid >> 4) * 4;
    float acc[4][4] = {};
#pragma unroll 8
    for (int k = 0; k < 64; k++) {
        float a[4], b[4];
#pragma unroll
        for (int i = 0; i < 4; i++) a[i] = Qs[ty + i][k];
#pragma unroll
        for (int j = 0; j < 4; j++) b[j] = Ks[tx + j][k];
#pragma unroll
        for (int i = 0; i < 4; i++)
#pragma unroll
            for (int j = 0; j < 4; j++)
                acc[i][j] = fmaf(a[i], b[j], acc[i][j]);
    }

#pragma unroll
    for (int i = 0; i < 4; i++) {
        int m = m0 + ty + i;
        if (m >= Nn) continue;
#pragma unroll
        for (int j = 0; j < 4; j++) {
            int n = n0 + tx + j;
            if (n >= Nn) continue;
            g_p[((size_t)bh * Nn + m) * PLD + n] =
                acc[i][j] + g_rpb[((size_t)h * Nn + m) * Nn + n];
        }
    }
}

// ---------------------------------------------------------------------------
// Kernel 4: softmax over last dim (197), one warp per row. Pads stay 0.
// ---------------------------------------------------------------------------
__global__ void softmax_kernel() {
    int gwarp = (blockIdx.x * blockDim.x + threadIdx.x) >> 5;
    int lane  = threadIdx.x & 31;
    const int rows = Bb * Hh * Nn;
    if (gwarp >= rows) return;
    float* row = g_p + (size_t)gwarp * PLD;
    float mx = -1e30f;
    for (int j = lane; j < Nn; j += 32) mx = fmaxf(mx, row[j]);
#pragma unroll
    for (int o = 16; o; o >>= 1) mx = fmaxf(mx, __shfl_xor_sync(0xffffffffu, mx, o));
    float s = 0.f;
    for (int j = lane; j < Nn; j += 32) {
        float e = __expf(row[j] - mx);
        row[j] = e;
        s += e;
    }
#pragma unroll
    for (int o = 16; o; o >>= 1) s += __shfl_xor_sync(0xffffffffu, s, o);
    float inv = 1.f / s;
    for (int j = lane; j < Nn; j += 32) row[j] *= inv;
}

// ---------------------------------------------------------------------------
// Kernel 5: O[bh] = P[bh] @ V[bh]  -> g_o in [B,N,C] layout
// ---------------------------------------------------------------------------
__global__ __launch_bounds__(256) void av_kernel() {
    __shared__ float Ps[64][33];
    __shared__ float Vs[32][64];
    const int bh = blockIdx.y;
    const int m0 = blockIdx.x * 64;
    const int bIdx = bh / Hh, h = bh % Hh;
    const int tid = threadIdx.x;
    const float* pbase = g_p + (size_t)bh * Nn * PLD;
    const float* vb    = g_v + (size_t)bh * Nn * Dd;

    const int tx = (tid & 15) * 4;
    const int ty = (tid >> 4) * 4;
    float acc[4][4] = {};

    for (int k0 = 0; k0 < Nn; k0 += 32) {
        {   // load P tile: 64 rows x 32 cols
            int r  = tid >> 2;
            int c0 = (tid & 3) * 8;
            int m = m0 + r;
#pragma unroll
            for (int ii = 0; ii < 2; ii++) {
                int kk = k0 + c0 + ii * 4;
                float4 v = (m < Nn && kk < Nn)
                    ? *(const float4*)(pbase + (size_t)m * PLD + kk)
                    : make_float4(0, 0, 0, 0);   // pad cols of P are zero
                Ps[r][c0 + ii * 4 + 0] = v.x; Ps[r][c0 + ii * 4 + 1] = v.y;
                Ps[r][c0 + ii * 4 + 2] = v.z; Ps[r][c0 + ii * 4 + 3] = v.w;
            }
        }
        {   // load V tile: 32 rows x 64 cols
            int r  = tid >> 3;          // 0..31
            int c0 = (tid & 7) * 8;
            int kk = k0 + r;
#pragma unroll
            for (int ii = 0; ii < 2; ii++) {
                float4 v = (kk < Nn)
                    ? *(const float4*)(vb + (size_t)kk * Dd + c0 + ii * 4)
                    : make_float4(0, 0, 0, 0);
                Vs[r][c0 + ii * 4 + 0] = v.x; Vs[r][c0 + ii * 4 + 1] = v.y;
                Vs[r][c0 + ii * 4 + 2] = v.z; Vs[r][c0 + ii * 4 + 3] = v.w;
            }
        }
        __syncthreads();
#pragma unroll 8
        for (int k = 0; k < 32; k++) {
            float a[4], b[4];
#pragma unroll
            for (int i = 0; i < 4; i++) a[i] = Ps[ty + i][k];
#pragma unroll
            for (int j = 0; j < 4; j++) b[j] = Vs[k][tx + j];
#pragma unroll
            for (int i = 0; i < 4; i++)
#pragma unroll
                for (int j = 0; j < 4; j++)
                    acc[i][j] = fmaf(a[i], b[j], acc[i][j]);
        }
        __syncthreads();
    }

#pragma unroll
    for (int i = 0; i < 4; i++) {
        int m = m0 + ty + i;
        if (m >= Nn) continue;
#pragma unroll
        for (int j = 0; j < 4; j++)
            g_o[((size_t)bIdx * Nn + m) * Cc + h * Dd + tx + j] = acc[i][j];
    }
}

// ---------------------------------------------------------------------------
extern "C" void kernel_launch(void* const* d_in, const int* in_sizes, int n_in,
                              void* d_out, int out_size)
{
    const float* x         = (const float*)d_in[0];
    const float* qkv_w     = (const float*)d_in[1];
    const float* q_bias    = (const float*)d_in[2];
    const float* k_bias    = (const float*)d_in[3];
    const float* v_bias    = (const float*)d_in[4];
    const float* rel_table = (const float*)d_in[5];
    const float* proj_w    = (const float*)d_in[6];
    const float* proj_b    = (const float*)d_in[7];
    float* out = (float*)d_out;

    // 1. relative position bias gather
    {
        int total = Hh * Nn * Nn;
        rpb_kernel<<<(total + 255) / 256, 256>>>(rel_table);
    }
    // 2. QKV projection + scatter (q pre-scaled)
    {
        dim3 grid(3 * Cc / 128, (M_TOT + 127) / 128);
        sgemm_kernel<0><<<grid, 256>>>(x, qkv_w, q_bias, k_bias, v_bias, nullptr);
    }
    // 3. attention scores + bias
    {
        dim3 grid((Nn + 63) / 64, (Nn + 63) / 64, Bb * Hh);
        scores_kernel<<<grid, 256>>>();
    }
    // 4. softmax
    {
        int rows = Bb * Hh * Nn;
        int warpsPerBlock = 8;
        softmax_kernel<<<(rows + warpsPerBlock - 1) / warpsPerBlock, warpsPerBlock * 32>>>();
    }
    // 5. attn @ V
    {
        dim3 grid((Nn + 63) / 64, Bb * Hh);
        av_kernel<<<grid, 256>>>();
    }
    // 6. output projection
    {
        dim3 grid(Cc / 128, (M_TOT + 127) / 128);
        sgemm_kernel<1><<<grid, 256>>>(nullptr, proj_w, proj_b, nullptr, nullptr, out);
    }
}

// round 2
// speedup vs baseline: 2.3003x; 2.3003x over previous
#include <cuda_runtime.h>
#include <cuda_bf16.h>
#include <cstddef>

// Problem constants
constexpr int Bb  = 64;
constexpr int Nn  = 197;
constexpr int Cc  = 768;
constexpr int Hh  = 12;
constexpr int Dd  = 64;
constexpr int M_TOT = Bb * Nn;        // 12608
constexpr int PLD  = 208;             // padded row stride for P

// Scratch (device globals; allocation-free per harness rules)
__device__ float g_q[(size_t)Bb * Hh * Nn * Dd];       // [B,H,N,D], pre-scaled
__device__ float g_k[(size_t)Bb * Hh * Nn * Dd];
__device__ float g_v[(size_t)Bb * Hh * Nn * Dd];
__device__ float g_p[(size_t)Bb * Hh * Nn * PLD];      // [BH, N, PLD]
__device__ float g_rpb[(size_t)Hh * Nn * Nn];          // [H, N, N]
__device__ float g_o[(size_t)Bb * Nn * Cc];            // [B, N, C]

// ---------------------------------------------------------------------------
// tf32 helpers
// ---------------------------------------------------------------------------
__device__ __forceinline__ unsigned f2tf(float f) {
    unsigned u;
    asm("cvt.rna.tf32.f32 %0, %1;" : "=r"(u) : "f"(f));
    return u;
}

__device__ __forceinline__ void mma_tf32(
    float& c0, float& c1, float& c2, float& c3,
    unsigned a0, unsigned a1, unsigned a2, unsigned a3,
    unsigned b0, unsigned b1)
{
    asm volatile(
        "mma.sync.aligned.m16n8k8.row.col.f32.tf32.tf32.f32 "
        "{%0,%1,%2,%3},{%4,%5,%6,%7},{%8,%9},{%0,%1,%2,%3};\n"
        : "+f"(c0), "+f"(c1), "+f"(c2), "+f"(c3)
        : "r"(a0), "r"(a1), "r"(a2), "r"(a3), "r"(b0), "r"(b1));
}

// ---------------------------------------------------------------------------
// Kernel 1: relative position bias gather
// ---------------------------------------------------------------------------
__global__ void rpb_kernel(const float* __restrict__ rel_table) {
    int tid = blockIdx.x * blockDim.x + threadIdx.x;
    const int total = Hh * Nn * Nn;
    if (tid >= total) return;
    int h = tid / (Nn * Nn);
    int r = tid % (Nn * Nn);
    int i = r / Nn, j = r % Nn;
    int idx;
    if (i == 0 && j == 0)      idx = 731;
    else if (i == 0)           idx = 729;
    else if (j == 0)           idx = 730;
    else {
        int a = i - 1, b = j - 1;
        int d0 = (a / 14 - b / 14) + 13;
        int d1 = (a % 14 - b % 14) + 13;
        idx = d0 * 27 + d1;
    }
    g_rpb[tid] = rel_table[idx * Hh + h];
}

// ---------------------------------------------------------------------------
// Kernels 2 & 6: tf32 tensor-core GEMM, C = A @ W^T (+bias)
// BM=128 BN=128 BK=32, 256 threads, 8 warps (4m x 2n), warp tile 32x64
// EPI==0: A = x (12608x768), W = qkv_w (2304x768), scatter q/k/v
// EPI==1: A = g_o, W = proj_w (768x768), out = A@W^T + proj_b
// ---------------------------------------------------------------------------
template <int EPI>
__global__ __launch_bounds__(256) void gemm_tf32(
    const float* __restrict__ Ain, const float* __restrict__ W,
    const float* __restrict__ b0v, const float* __restrict__ b1v,
    const float* __restrict__ b2v, float* __restrict__ out)
{
    constexpr int K = 768, BM = 128, BN = 128, BK = 32;
    __shared__ unsigned As[BM][BK + 4];   // stride 36: conflict-free frag reads
    __shared__ unsigned Bs[BN][BK + 4];

    const float* A = (EPI == 0) ? Ain : (const float*)g_o;
    const int tid  = threadIdx.x;
    const int bm   = blockIdx.y * BM;
    const int bn   = blockIdx.x * BN;
    const int w    = tid >> 5, lane = tid & 31;
    const int wm   = w >> 1, wn = w & 1;
    const int m0w  = wm * 32, n0w = wn * 64;
    const int r    = lane >> 2, cg = lane & 3;

    float acc[2][8][4];
#pragma unroll
    for (int i = 0; i < 2; i++)
#pragma unroll
        for (int j = 0; j < 8; j++)
#pragma unroll
            for (int t = 0; t < 4; t++) acc[i][j][t] = 0.f;

    float4 sa[4], sb[4];
#pragma unroll
    for (int i = 0; i < 4; i++) {
        int s = tid + i * 256;
        int row = s >> 3, kc = (s & 7) * 4;
        int gm = bm + row;
        sa[i] = (gm < M_TOT) ? *(const float4*)(A + (size_t)gm * K + kc)
                             : make_float4(0, 0, 0, 0);
        sb[i] = *(const float4*)(W + (size_t)(bn + row) * K + kc);
    }

    for (int kc0 = 0; kc0 < K; kc0 += BK) {
#pragma unroll
        for (int i = 0; i < 4; i++) {
            int s = tid + i * 256;
            int row = s >> 3, kc = (s & 7) * 4;
            *(uint4*)&As[row][kc] =
                make_uint4(f2tf(sa[i].x), f2tf(sa[i].y), f2tf(sa[i].z), f2tf(sa[i].w));
            *(uint4*)&Bs[row][kc] =
                make_uint4(f2tf(sb[i].x), f2tf(sb[i].y), f2tf(sb[i].z), f2tf(sb[i].w));
        }
        __syncthreads();

        if (kc0 + BK < K) {
#pragma unroll
            for (int i = 0; i < 4; i++) {
                int s = tid + i * 256;
                int row = s >> 3, kc = (s & 7) * 4;
                int gm = bm + row;
                sa[i] = (gm < M_TOT)
                    ? *(const float4*)(A + (size_t)gm * K + kc0 + BK + kc)
                    : make_float4(0, 0, 0, 0);
                sb[i] = *(const float4*)(W + (size_t)(bn + row) * K + kc0 + BK + kc);
            }
        }

#pragma unroll
        for (int ks = 0; ks < BK; ks += 8) {
            unsigned af[2][4], bf[8][2];
#pragma unroll
            for (int mt = 0; mt < 2; mt++) {
                int rb = m0w + mt * 16;
                af[mt][0] = As[rb + r][ks + cg];
                af[mt][1] = As[rb + r + 8][ks + cg];
                af[mt][2] = As[rb + r][ks + cg + 4];
                af[mt][3] = As[rb + r + 8][ks + cg + 4];
            }
#pragma unroll
            for (int nt = 0; nt < 8; nt++) {
                int nb = n0w + nt * 8;
                bf[nt][0] = Bs[nb + r][ks + cg];
                bf[nt][1] = Bs[nb + r][ks + cg + 4];
            }
#pragma unroll
            for (int mt = 0; mt < 2; mt++)
#pragma unroll
                for (int nt = 0; nt < 8; nt++)
                    mma_tf32(acc[mt][nt][0], acc[mt][nt][1],
                             acc[mt][nt][2], acc[mt][nt][3],
                             af[mt][0], af[mt][1], af[mt][2], af[mt][3],
                             bf[nt][0], bf[nt][1]);
        }
        __syncthreads();
    }

    // Epilogue
#pragma unroll
    for (int mt = 0; mt < 2; mt++) {
        int mbase = bm + m0w + mt * 16;
#pragma unroll
        for (int nt = 0; nt < 8; nt++) {
            int nbase = bn + n0w + nt * 8 + 2 * cg;
#pragma unroll
            for (int half = 0; half < 2; half++) {
                int row = mbase + r + half * 8;
                if (row >= M_TOT) continue;
                float v0 = acc[mt][nt][half * 2 + 0];
                float v1 = acc[mt][nt][half * 2 + 1];
                if (EPI == 1) {
                    out[(size_t)row * Cc + nbase]     = v0 + b0v[nbase];
                    out[(size_t)row * Cc + nbase + 1] = v1 + b0v[nbase + 1];
                } else {
                    int bI = row / Nn, n = row % Nn;
#pragma unroll
                    for (int e = 0; e < 2; e++) {
                        int c = nbase + e;
                        float v = e ? v1 : v0;
                        int which = c / Cc;
                        int cc = c % Cc;
                        int h = cc >> 6, d = cc & 63;
                        size_t off = (((size_t)bI * Hh + h) * Nn + n) * Dd + d;
                        if (which == 0)      g_q[off] = (v + b0v[cc]) * 0.125f;
                        else if (which == 1) g_k[off] = v + b1v[cc];
                        else                 g_v[off] = v + b2v[cc];
                    }
                }
            }
        }
    }
}

// ---------------------------------------------------------------------------
// Kernel 3: scores  S = q @ k^T + rpb  (tf32 mma), zero-pads cols [197,208)
// 64x64 tile, K=64 resident. 128 threads, 4 warps (2x2), warp tile 32x32
// ---------------------------------------------------------------------------
__global__ __launch_bounds__(128) void scores_tf32() {
    __shared__ unsigned Qs[64][68];
    __shared__ unsigned Ks[64][68];
    const int bh = blockIdx.z, h = bh % Hh;
    const int m0 = blockIdx.y * 64, n0 = blockIdx.x * 64;
    const int tid = threadIdx.x, lane = tid & 31, w = tid >> 5;
    const int wm = w >> 1, wn = w & 1;
    const int r = lane >> 2, cg = lane & 3;
    const float* qb = g_q + (size_t)bh * Nn * Dd;
    const float* kb = g_k + (size_t)bh * Nn * Dd;

#pragma unroll
    for (int i = 0; i < 8; i++) {
        int s = tid + i * 128;
        int row = s >> 4, kc = (s & 15) * 4;
        float4 qv = (m0 + row < Nn)
            ? *(const float4*)(qb + (size_t)(m0 + row) * Dd + kc)
            : make_float4(0, 0, 0, 0);
        *(uint4*)&Qs[row][kc] =
            make_uint4(f2tf(qv.x), f2tf(qv.y), f2tf(qv.z), f2tf(qv.w));
        float4 kv = (n0 + row < Nn)
            ? *(const float4*)(kb + (size_t)(n0 + row) * Dd + kc)
            : make_float4(0, 0, 0, 0);
        *(uint4*)&Ks[row][kc] =
            make_uint4(f2tf(kv.x), f2tf(kv.y), f2tf(kv.z), f2tf(kv.w));
    }
    __syncthreads();

    float acc[2][4][4];
#pragma unroll
    for (int i = 0; i < 2; i++)
#pragma unroll
        for (int j = 0; j < 4; j++)
#pragma unroll
            for (int t = 0; t < 4; t++) acc[i][j][t] = 0.f;

#pragma unroll
    for (int ks = 0; ks < 64; ks += 8) {
        unsigned af[2][4], bf[4][2];
#pragma unroll
        for (int mt = 0; mt < 2; mt++) {
            int rb = wm * 32 + mt * 16;
            af[mt][0] = Qs[rb + r][ks + cg];
            af[mt][1] = Qs[rb + r + 8][ks + cg];
            af[mt][2] = Qs[rb + r][ks + cg + 4];
            af[mt][3] = Qs[rb + r + 8][ks + cg + 4];
        }
#pragma unroll
        for (int nt = 0; nt < 4; nt++) {
            int nb = wn * 32 + nt * 8;
            bf[nt][0] = Ks[nb + r][ks + cg];
            bf[nt][1] = Ks[nb + r][ks + cg + 4];
        }
#pragma unroll
        for (int mt = 0; mt < 2; mt++)
#pragma unroll
            for (int nt = 0; nt < 4; nt++)
                mma_tf32(acc[mt][nt][0], acc[mt][nt][1],
                         acc[mt][nt][2], acc[mt][nt][3],
                         af[mt][0], af[mt][1], af[mt][2], af[mt][3],
                         bf[nt][0], bf[nt][1]);
    }

#pragma unroll
    for (int mt = 0; mt < 2; mt++) {
        int mbase = m0 + wm * 32 + mt * 16;
#pragma unroll
        for (int nt = 0; nt < 4; nt++) {
            int nbase = n0 + wn * 32 + nt * 8 + 2 * cg;
#pragma unroll
            for (int half = 0; half < 2; half++) {
                int m = mbase + r + half * 8;
                if (m >= Nn) continue;
#pragma unroll
                for (int e = 0; e < 2; e++) {
                    int n = nbase + e;
                    if (n >= PLD) continue;
                    float v = acc[mt][nt][half * 2 + e];
                    g_p[((size_t)bh * Nn + m) * PLD + n] =
                        (n < Nn) ? v + g_rpb[((size_t)h * Nn + m) * Nn + n] : 0.f;
                }
            }
        }
    }
}

// ---------------------------------------------------------------------------
// Kernel 4: softmax over last dim (197), one warp per row
// ---------------------------------------------------------------------------
__global__ void softmax_kernel() {
    int gwarp = (blockIdx.x * blockDim.x + threadIdx.x) >> 5;
    int lane  = threadIdx.x & 31;
    const int rows = Bb * Hh * Nn;
    if (gwarp >= rows) return;
    float* row = g_p + (size_t)gwarp * PLD;
    float mx = -1e30f;
    for (int j = lane; j < Nn; j += 32) mx = fmaxf(mx, row[j]);
#pragma unroll
    for (int o = 16; o; o >>= 1) mx = fmaxf(mx, __shfl_xor_sync(0xffffffffu, mx, o));
    float s = 0.f;
    for (int j = lane; j < Nn; j += 32) {
        float e = __expf(row[j] - mx);
        row[j] = e;
        s += e;
    }
#pragma unroll
    for (int o = 16; o; o >>= 1) s += __shfl_xor_sync(0xffffffffu, s, o);
    float inv = 1.f / s;
    for (int j = lane; j < Nn; j += 32) row[j] *= inv;
}

// ---------------------------------------------------------------------------
// Kernel 5: O = P @ V (tf32 mma) -> g_o [B,N,C]
// 64(m) x 64(n=D) tile, k chunks of 32. 128 threads, 4 warps (2x2)
// ---------------------------------------------------------------------------
__global__ __launch_bounds__(128) void av_tf32() {
    __shared__ unsigned Ps[64][36];
    __shared__ unsigned Vs[64][36];   // Vs[d][token]
    const int bh = blockIdx.y, m0 = blockIdx.x * 64;
    const int bI = bh / Hh, h = bh % Hh;
    const int tid = threadIdx.x, lane = tid & 31, w = tid >> 5;
    const int wm = w >> 1, wn = w & 1;
    const int r = lane >> 2, cg = lane & 3;
    const float* pb = g_p + (size_t)bh * Nn * PLD;
    const float* vb = g_v + (size_t)bh * Nn * Dd;

    float acc[2][4][4];
#pragma unroll
    for (int i = 0; i < 2; i++)
#pragma unroll
        for (int j = 0; j < 4; j++)
#pragma unroll
            for (int t = 0; t < 4; t++) acc[i][j][t] = 0.f;

    for (int k0 = 0; k0 < 224; k0 += 32) {
#pragma unroll
        for (int i = 0; i < 4; i++) {         // P tile 64x32
            int s = tid + i * 128;
            int row = s >> 3, kc = (s & 7) * 4;
            int m = m0 + row, kk = k0 + kc;
            float4 pv = (m < Nn && kk < PLD)
                ? *(const float4*)(pb + (size_t)m * PLD + kk)
                : make_float4(0, 0, 0, 0);
            *(uint4*)&Ps[row][kc] =
                make_uint4(f2tf(pv.x), f2tf(pv.y), f2tf(pv.z), f2tf(pv.w));
        }
#pragma unroll
        for (int i = 0; i < 4; i++) {         // V tile 32x64 -> Vs[d][tok]
            int s = tid + i * 128;
            int tok = s >> 4, dc = (s & 15) * 4;
            int kk = k0 + tok;
            float4 vv = (kk < Nn)
                ? *(const float4*)(vb + (size_t)kk * Dd + dc)
                : make_float4(0, 0, 0, 0);
            Vs[dc + 0][tok] = f2tf(vv.x);
            Vs[dc + 1][tok] = f2tf(vv.y);
            Vs[dc + 2][tok] = f2tf(vv.z);
            Vs[dc + 3][tok] = f2tf(vv.w);
        }
        __syncthreads();

#pragma unroll
        for (int ks = 0; ks < 32; ks += 8) {
            unsigned af[2][4], bf[4][2];
#pragma unroll
            for (int mt = 0; mt < 2; mt++) {
                int rb = wm * 32 + mt * 16;
                af[mt][0] = Ps[rb + r][ks + cg];
                af[mt][1] = Ps[rb + r + 8][ks + cg];
                af[mt][2] = Ps[rb + r][ks + cg + 4];
                af[mt][3] = Ps[rb + r + 8][ks + cg + 4];
            }
#pragma unroll
            for (int nt = 0; nt < 4; nt++) {
                int nb = wn * 32 + nt * 8;
                bf[nt][0] = Vs[nb + r][ks + cg];
                bf[nt][1] = Vs[nb + r][ks + cg + 4];
            }
#pragma unroll
            for (int mt = 0; mt < 2; mt++)
#pragma unroll
                for (int nt = 0; nt < 4; nt++)
                    mma_tf32(acc[mt][nt][0], acc[mt][nt][1],
                             acc[mt][nt][2], acc[mt][nt][3],
                             af[mt][0], af[mt][1], af[mt][2], af[mt][3],
                             bf[nt][0], bf[nt][1]);
        }
        __syncthreads();
    }

#pragma unroll
    for (int mt = 0; mt < 2; mt++) {
        int mbase = m0 + wm * 32 + mt * 16;
#pragma unroll
        for (int nt = 0; nt < 4; nt++) {
            int nb = wn * 32 + nt * 8 + 2 * cg;
#pragma unroll
            for (int half = 0; half < 2; half++) {
                int m = mbase + r + half * 8;
                if (m >= Nn) continue;
                size_t o = ((size_t)bI * Nn + m) * Cc + h * Dd + nb;
                g_o[o]     = acc[mt][nt][half * 2 + 0];
                g_o[o + 1] = acc[mt][nt][half * 2 + 1];
            }
        }
    }
}

// ---------------------------------------------------------------------------
extern "C" void kernel_launch(void* const* d_in, const int* in_sizes, int n_in,
                              void* d_out, int out_size)
{
    const float* x         = (const float*)d_in[0];
    const float* qkv_w     = (const float*)d_in[1];
    const float* q_bias    = (const float*)d_in[2];
    const float* k_bias    = (const float*)d_in[3];
    const float* v_bias    = (const float*)d_in[4];
    const float* rel_table = (const float*)d_in[5];
    const float* proj_w    = (const float*)d_in[6];
    const float* proj_b    = (const float*)d_in[7];
    float* out = (float*)d_out;

    {
        int total = Hh * Nn * Nn;
        rpb_kernel<<<(total + 255) / 256, 256>>>(rel_table);
    }
    {
        dim3 grid(3 * Cc / 128, (M_TOT + 127) / 128);
        gemm_tf32<0><<<grid, 256>>>(x, qkv_w, q_bias, k_bias, v_bias, nullptr);
    }
    {
        dim3 grid((Nn + 63) / 64, (Nn + 63) / 64, Bb * Hh);
        scores_tf32<<<grid, 128>>>();
    }
    {
        int rows = Bb * Hh * Nn;
        softmax_kernel<<<(rows + 7) / 8, 256>>>();
    }
    {
        dim3 grid((Nn + 63) / 64, Bb * Hh);
        av_tf32<<<grid, 128>>>();
    }
    {
        dim3 grid(Cc / 128, (M_TOT + 127) / 128);
        gemm_tf32<1><<<grid, 256>>>(nullptr, proj_w, proj_b, nullptr, nullptr, out);
    }
}

// round 3
// speedup vs baseline: 2.4874x; 1.0814x over previous
#include <cuda_runtime.h>
#include <cuda_bf16.h>
#include <cstddef>

// Problem constants
constexpr int Bb  = 64;
constexpr int Nn  = 197;
constexpr int Cc  = 768;
constexpr int Hh  = 12;
constexpr int Dd  = 64;
constexpr int M_TOT = Bb * Nn;        // 12608
constexpr int SLD  = 260;             // S row stride (floats) in fused kernel smem

// Scratch (device globals; allocation-free per harness rules)
__device__ float g_q[(size_t)Bb * Hh * Nn * Dd];       // [B,H,N,D], pre-scaled
__device__ float g_k[(size_t)Bb * Hh * Nn * Dd];
__device__ float g_v[(size_t)Bb * Hh * Nn * Dd];
__device__ float g_rpb[(size_t)Hh * Nn * Nn];          // [H, N, N]
__device__ float g_o[(size_t)Bb * Nn * Cc];            // [B, N, C]

// ---------------------------------------------------------------------------
// tf32 helpers
// ---------------------------------------------------------------------------
__device__ __forceinline__ unsigned f2tf(float f) {
    unsigned u;
    asm("cvt.rna.tf32.f32 %0, %1;" : "=r"(u) : "f"(f));
    return u;
}

__device__ __forceinline__ void mma_tf32(
    float& c0, float& c1, float& c2, float& c3,
    unsigned a0, unsigned a1, unsigned a2, unsigned a3,
    unsigned b0, unsigned b1)
{
    asm volatile(
        "mma.sync.aligned.m16n8k8.row.col.f32.tf32.tf32.f32 "
        "{%0,%1,%2,%3},{%4,%5,%6,%7},{%8,%9},{%0,%1,%2,%3};\n"
        : "+f"(c0), "+f"(c1), "+f"(c2), "+f"(c3)
        : "r"(a0), "r"(a1), "r"(a2), "r"(a3), "r"(b0), "r"(b1));
}

// ---------------------------------------------------------------------------
// Kernel 1: relative position bias gather
// ---------------------------------------------------------------------------
__global__ void rpb_kernel(const float* __restrict__ rel_table) {
    int tid = blockIdx.x * blockDim.x + threadIdx.x;
    const int total = Hh * Nn * Nn;
    if (tid >= total) return;
    int h = tid / (Nn * Nn);
    int r = tid % (Nn * Nn);
    int i = r / Nn, j = r % Nn;
    int idx;
    if (i == 0 && j == 0)      idx = 731;
    else if (i == 0)           idx = 729;
    else if (j == 0)           idx = 730;
    else {
        int a = i - 1, b = j - 1;
        int d0 = (a / 14 - b / 14) + 13;
        int d1 = (a % 14 - b % 14) + 13;
        idx = d0 * 27 + d1;
    }
    g_rpb[tid] = rel_table[idx * Hh + h];
}

// ---------------------------------------------------------------------------
// Kernels 2 & 4: tf32 GEMM C = A @ W^T (+bias), ping-pong smem (1 sync/iter)
// BM=128 BN=128 BK=32, 256 threads, 8 warps (4m x 2n), warp tile 32x64
// EPI==0: A = x (12608x768), W = qkv_w (2304x768), scatter q/k/v
// EPI==1: A = g_o, W = proj_w (768x768), out = A@W^T + proj_b
// dynamic smem: 4 * 128*36 u32 = 73728 B  (As0, As1, Bs0, Bs1)
// ---------------------------------------------------------------------------
template <int EPI>
__global__ __launch_bounds__(256) void gemm_tf32(
    const float* __restrict__ Ain, const float* __restrict__ W,
    const float* __restrict__ b0v, const float* __restrict__ b1v,
    const float* __restrict__ b2v, float* __restrict__ out)
{
    constexpr int K = 768, BM = 128, BK = 32;
    constexpr int TSTR = BK + 4;       // 36
    constexpr int BUFSZ = BM * TSTR;   // 4608 u32
    extern __shared__ unsigned gsm[];
    unsigned* Asb = gsm;               // [2][128][36]
    unsigned* Bsb = gsm + 2 * BUFSZ;   // [2][128][36]

    const float* A = (EPI == 0) ? Ain : (const float*)g_o;
    const int tid  = threadIdx.x;
    const int bm   = blockIdx.y * BM;
    const int bn   = blockIdx.x * BM;
    const int w    = tid >> 5, lane = tid & 31;
    const int wm   = w >> 1, wn = w & 1;
    const int m0w  = wm * 32, n0w = wn * 64;
    const int r    = lane >> 2, cg = lane & 3;

    float acc[2][8][4];
#pragma unroll
    for (int i = 0; i < 2; i++)
#pragma unroll
        for (int j = 0; j < 8; j++)
#pragma unroll
            for (int t = 0; t < 4; t++) acc[i][j][t] = 0.f;

    const int srow = tid >> 3;          // 0..31 step over 4 iters -> 128 rows
    const int skc  = (tid & 7) * 4;

    float4 sa[4], sb[4];
#pragma unroll
    for (int i = 0; i < 4; i++) {
        int row = srow + i * 32;
        int gm = bm + row;
        sa[i] = (gm < M_TOT) ? *(const float4*)(A + (size_t)gm * K + skc)
                             : make_float4(0, 0, 0, 0);
        sb[i] = *(const float4*)(W + (size_t)(bn + row) * K + skc);
    }
    // store chunk 0 into buf 0
#pragma unroll
    for (int i = 0; i < 4; i++) {
        int row = srow + i * 32;
        *(uint4*)&Asb[row * TSTR + skc] =
            make_uint4(f2tf(sa[i].x), f2tf(sa[i].y), f2tf(sa[i].z), f2tf(sa[i].w));
        *(uint4*)&Bsb[row * TSTR + skc] =
            make_uint4(f2tf(sb[i].x), f2tf(sb[i].y), f2tf(sb[i].z), f2tf(sb[i].w));
    }
    __syncthreads();

    int buf = 0;
    for (int kc0 = 0; kc0 < K; kc0 += BK) {
        const bool more = (kc0 + BK) < K;
        if (more) {
#pragma unroll
            for (int i = 0; i < 4; i++) {
                int row = srow + i * 32;
                int gm = bm + row;
                sa[i] = (gm < M_TOT)
                    ? *(const float4*)(A + (size_t)gm * K + kc0 + BK + skc)
                    : make_float4(0, 0, 0, 0);
                sb[i] = *(const float4*)(W + (size_t)(bn + row) * K + kc0 + BK + skc);
            }
        }

        const unsigned* As = Asb + buf * BUFSZ;
        const unsigned* Bs = Bsb + buf * BUFSZ;
#pragma unroll
        for (int ks = 0; ks < BK; ks += 8) {
            unsigned af[2][4], bf[8][2];
#pragma unroll
            for (int mt = 0; mt < 2; mt++) {
                int rb = m0w + mt * 16;
                af[mt][0] = As[(rb + r) * TSTR + ks + cg];
                af[mt][1] = As[(rb + r + 8) * TSTR + ks + cg];
                af[mt][2] = As[(rb + r) * TSTR + ks + cg + 4];
                af[mt][3] = As[(rb + r + 8) * TSTR + ks + cg + 4];
            }
#pragma unroll
            for (int nt = 0; nt < 8; nt++) {
                int nb = n0w + nt * 8;
                bf[nt][0] = Bs[(nb + r) * TSTR + ks + cg];
                bf[nt][1] = Bs[(nb + r) * TSTR + ks + cg + 4];
            }
#pragma unroll
            for (int mt = 0; mt < 2; mt++)
#pragma unroll
                for (int nt = 0; nt < 8; nt++)
                    mma_tf32(acc[mt][nt][0], acc[mt][nt][1],
                             acc[mt][nt][2], acc[mt][nt][3],
                             af[mt][0], af[mt][1], af[mt][2], af[mt][3],
                             bf[nt][0], bf[nt][1]);
        }

        if (more) {
            unsigned* An = Asb + (buf ^ 1) * BUFSZ;
            unsigned* Bn = Bsb + (buf ^ 1) * BUFSZ;
#pragma unroll
            for (int i = 0; i < 4; i++) {
                int row = srow + i * 32;
                *(uint4*)&An[row * TSTR + skc] =
                    make_uint4(f2tf(sa[i].x), f2tf(sa[i].y), f2tf(sa[i].z), f2tf(sa[i].w));
                *(uint4*)&Bn[row * TSTR + skc] =
                    make_uint4(f2tf(sb[i].x), f2tf(sb[i].y), f2tf(sb[i].z), f2tf(sb[i].w));
            }
            __syncthreads();
            buf ^= 1;
        }
    }

    // Epilogue
#pragma unroll
    for (int mt = 0; mt < 2; mt++) {
        int mbase = bm + m0w + mt * 16;
#pragma unroll
        for (int nt = 0; nt < 8; nt++) {
            int nbase = bn + n0w + nt * 8 + 2 * cg;
#pragma unroll
            for (int half = 0; half < 2; half++) {
                int row = mbase + r + half * 8;
                if (row >= M_TOT) continue;
                float v0 = acc[mt][nt][half * 2 + 0];
                float v1 = acc[mt][nt][half * 2 + 1];
                if (EPI == 1) {
                    out[(size_t)row * Cc + nbase]     = v0 + b0v[nbase];
                    out[(size_t)row * Cc + nbase + 1] = v1 + b0v[nbase + 1];
                } else {
                    int bI = row / Nn, n = row % Nn;
#pragma unroll
                    for (int e = 0; e < 2; e++) {
                        int c = nbase + e;
                        float v = e ? v1 : v0;
                        int which = c / Cc;
                        int cc = c % Cc;
                        int h = cc >> 6, d = cc & 63;
                        size_t off = (((size_t)bI * Hh + h) * Nn + n) * Dd + d;
                        if (which == 0)      g_q[off] = (v + b0v[cc]) * 0.125f;
                        else if (which == 1) g_k[off] = v + b1v[cc];
                        else                 g_v[off] = v + b2v[cc];
                    }
                }
            }
        }
    }
}

// ---------------------------------------------------------------------------
// Kernel 3: fused attention per (bh, 64-row tile):
//   S = Q@K^T + rpb  (smem)  -> softmax (smem, in-place, re-encoded tf32)
//   O = P@V -> g_o
// 128 threads (4 warps, 2x2). Dynamic smem:
//   Qs [64][68] u32 (17408B) | KVs [64][72] u32 (18432B) | Ss [64][260] f32 (66560B)
//   total 102400 B
// ---------------------------------------------------------------------------
__global__ __launch_bounds__(128) void attn_fused() {
    extern __shared__ unsigned smemu[];
    unsigned* Qs  = smemu;                 // stride 68
    unsigned* KVs = smemu + 64 * 68;       // stride 72
    float*    Ss  = (float*)(KVs + 64 * 72); // stride SLD=260
    unsigned* Su  = (unsigned*)Ss;

    const int bh = blockIdx.y, h = bh % Hh, bI = bh / Hh;
    const int m0 = blockIdx.x * 64;
    const int tid = threadIdx.x, lane = tid & 31, w = tid >> 5;
    const int wm = w >> 1, wn = w & 1;
    const int r = lane >> 2, cg = lane & 3;
    const float* qb = g_q + (size_t)bh * Nn * Dd;
    const float* kb = g_k + (size_t)bh * Nn * Dd;
    const float* vb = g_v + (size_t)bh * Nn * Dd;

    // ---- load Q tile (tf32) ----
#pragma unroll
    for (int i = 0; i < 8; i++) {
        int s = tid + i * 128;
        int row = s >> 4, kc = (s & 15) * 4;
        float4 qv = (m0 + row < Nn)
            ? *(const float4*)(qb + (size_t)(m0 + row) * Dd + kc)
            : make_float4(0, 0, 0, 0);
        *(uint4*)&Qs[row * 68 + kc] =
            make_uint4(f2tf(qv.x), f2tf(qv.y), f2tf(qv.z), f2tf(qv.w));
    }

    // ---- scores: 4 K-tiles of 64 cols ----
    for (int nt0 = 0; nt0 < 4; nt0++) {
        const int n0 = nt0 * 64;
#pragma unroll
        for (int i = 0; i < 8; i++) {
            int s = tid + i * 128;
            int row = s >> 4, kc = (s & 15) * 4;
            float4 kv = (n0 + row < Nn)
                ? *(const float4*)(kb + (size_t)(n0 + row) * Dd + kc)
                : make_float4(0, 0, 0, 0);
            *(uint4*)&KVs[row * 72 + kc] =
                make_uint4(f2tf(kv.x), f2tf(kv.y), f2tf(kv.z), f2tf(kv.w));
        }
        __syncthreads();

        float acc[2][4][4];
#pragma unroll
        for (int i = 0; i < 2; i++)
#pragma unroll
            for (int j = 0; j < 4; j++)
#pragma unroll
                for (int t = 0; t < 4; t++) acc[i][j][t] = 0.f;

#pragma unroll
        for (int ks = 0; ks < 64; ks += 8) {
            unsigned af[2][4], bf[4][2];
#pragma unroll
            for (int mt = 0; mt < 2; mt++) {
                int rb = wm * 32 + mt * 16;
                af[mt][0] = Qs[(rb + r) * 68 + ks + cg];
                af[mt][1] = Qs[(rb + r + 8) * 68 + ks + cg];
                af[mt][2] = Qs[(rb + r) * 68 + ks + cg + 4];
                af[mt][3] = Qs[(rb + r + 8) * 68 + ks + cg + 4];
            }
#pragma unroll
            for (int nt = 0; nt < 4; nt++) {
                int nb = wn * 32 + nt * 8;
                bf[nt][0] = KVs[(nb + r) * 72 + ks + cg];
                bf[nt][1] = KVs[(nb + r) * 72 + ks + cg + 4];
            }
#pragma unroll
            for (int mt = 0; mt < 2; mt++)
#pragma unroll
                for (int nt = 0; nt < 4; nt++)
                    mma_tf32(acc[mt][nt][0], acc[mt][nt][1],
                             acc[mt][nt][2], acc[mt][nt][3],
                             af[mt][0], af[mt][1], af[mt][2], af[mt][3],
                             bf[nt][0], bf[nt][1]);
        }

        // write S tile (+rpb); invalid cells -> 0
#pragma unroll
        for (int mt = 0; mt < 2; mt++) {
            int mlb = wm * 32 + mt * 16;
#pragma unroll
            for (int nt = 0; nt < 4; nt++) {
                int nl = wn * 32 + nt * 8 + 2 * cg;
#pragma unroll
                for (int half = 0; half < 2; half++) {
                    int ml = mlb + r + half * 8;
                    int mg = m0 + ml;
                    float v0 = 0.f, v1 = 0.f;
                    if (mg < Nn) {
                        int ng0 = n0 + nl, ng1 = ng0 + 1;
                        const float* rp = g_rpb + ((size_t)h * Nn + mg) * Nn;
                        if (ng0 < Nn) v0 = acc[mt][nt][half * 2 + 0] + rp[ng0];
                        if (ng1 < Nn) v1 = acc[mt][nt][half * 2 + 1] + rp[ng1];
                    }
                    *(float2*)&Ss[ml * SLD + n0 + nl] = make_float2(v0, v1);
                }
            }
        }
        __syncthreads();
    }

    // ---- softmax: one warp per row (rows w, w+4, ...) ----
    for (int row = w; row < 64; row += 4) {
        float* sr = Ss + row * SLD;
        float mx = -1e30f;
        for (int j = lane; j < Nn; j += 32) mx = fmaxf(mx, sr[j]);
#pragma unroll
        for (int o = 16; o; o >>= 1) mx = fmaxf(mx, __shfl_xor_sync(0xffffffffu, mx, o));
        float s = 0.f;
        for (int j = lane; j < Nn; j += 32) {
            float e = __expf(sr[j] - mx);
            sr[j] = e;
            s += e;
        }
#pragma unroll
        for (int o = 16; o; o >>= 1) s += __shfl_xor_sync(0xffffffffu, s, o);
        float inv = 1.f / s;
        for (int j = lane; j < Nn; j += 32) {
            unsigned u = f2tf(sr[j] * inv);
            ((unsigned*)sr)[j] = u;
        }
        // pad cols [197,256) were written 0.0f -> bit pattern 0 == tf32 zero
    }
    __syncthreads();

    // ---- PV: O = P @ V over 4 chunks of 64 ----
    float acc[2][4][4];
#pragma unroll
    for (int i = 0; i < 2; i++)
#pragma unroll
        for (int j = 0; j < 4; j++)
#pragma unroll
            for (int t = 0; t < 4; t++) acc[i][j][t] = 0.f;

    for (int k0 = 0; k0 < 256; k0 += 64) {
        if (k0) __syncthreads();   // protect KVs reuse across chunks
        // stage V rows k0..k0+63 as KVs[tok][d] (tf32)
#pragma unroll
        for (int i = 0; i < 8; i++) {
            int s = tid + i * 128;
            int tok = s >> 4, dc = (s & 15) * 4;
            int kk = k0 + tok;
            float4 vv = (kk < Nn)
                ? *(const float4*)(vb + (size_t)kk * Dd + dc)
                : make_float4(0, 0, 0, 0);
            *(uint4*)&KVs[tok * 72 + dc] =
                make_uint4(f2tf(vv.x), f2tf(vv.y), f2tf(vv.z), f2tf(vv.w));
        }
        __syncthreads();

#pragma unroll
        for (int ks = 0; ks < 64; ks += 8) {
            unsigned af[2][4], bf[4][2];
#pragma unroll
            for (int mt = 0; mt < 2; mt++) {
                int rb = wm * 32 + mt * 16;
                af[mt][0] = Su[(rb + r) * SLD + k0 + ks + cg];
                af[mt][1] = Su[(rb + r + 8) * SLD + k0 + ks + cg];
                af[mt][2] = Su[(rb + r) * SLD + k0 + ks + cg + 4];
                af[mt][3] = Su[(rb + r + 8) * SLD + k0 + ks + cg + 4];
            }
#pragma unroll
            for (int nt = 0; nt < 4; nt++) {
                int nb = wn * 32 + nt * 8;
                // B element (k=ks+cg, n=nb+r) from KVs[tok=k][d=n]
                bf[nt][0] = KVs[(ks + cg) * 72 + nb + r];
                bf[nt][1] = KVs[(ks + cg + 4) * 72 + nb + r];
            }
#pragma unroll
            for (int mt = 0; mt < 2; mt++)
#pragma unroll
                for (int nt = 0; nt < 4; nt++)
                    mma_tf32(acc[mt][nt][0], acc[mt][nt][1],
                             acc[mt][nt][2], acc[mt][nt][3],
                             af[mt][0], af[mt][1], af[mt][2], af[mt][3],
                             bf[nt][0], bf[nt][1]);
        }
    }

    // ---- store O tile to g_o [B,N,C] ----
#pragma unroll
    for (int mt = 0; mt < 2; mt++) {
        int mbase = m0 + wm * 32 + mt * 16;
#pragma unroll
        for (int nt = 0; nt < 4; nt++) {
            int nb = wn * 32 + nt * 8 + 2 * cg;
#pragma unroll
            for (int half = 0; half < 2; half++) {
                int m = mbase + r + half * 8;
                if (m >= Nn) continue;
                size_t o = ((size_t)bI * Nn + m) * Cc + h * Dd + nb;
                *(float2*)&g_o[o] = make_float2(acc[mt][nt][half * 2 + 0],
                                                acc[mt][nt][half * 2 + 1]);
            }
        }
    }
}

// ---------------------------------------------------------------------------
extern "C" void kernel_launch(void* const* d_in, const int* in_sizes, int n_in,
                              void* d_out, int out_size)
{
    const float* x         = (const float*)d_in[0];
    const float* qkv_w     = (const float*)d_in[1];
    const float* q_bias    = (const float*)d_in[2];
    const float* k_bias    = (const float*)d_in[3];
    const float* v_bias    = (const float*)d_in[4];
    const float* rel_table = (const float*)d_in[5];
    const float* proj_w    = (const float*)d_in[6];
    const float* proj_b    = (const float*)d_in[7];
    float* out = (float*)d_out;

    constexpr int GEMM_SMEM = 4 * 128 * 36 * 4;        // 73728
    constexpr int ATTN_SMEM = (64 * 68 + 64 * 72) * 4 + 64 * SLD * 4; // 102400

    static bool attr_done = false;
    if (!attr_done) {
        cudaFuncSetAttribute(gemm_tf32<0>, cudaFuncAttributeMaxDynamicSharedMemorySize, GEMM_SMEM);
        cudaFuncSetAttribute(gemm_tf32<1>, cudaFuncAttributeMaxDynamicSharedMemorySize, GEMM_SMEM);
        cudaFuncSetAttribute(attn_fused,   cudaFuncAttributeMaxDynamicSharedMemorySize, ATTN_SMEM);
        attr_done = true;
    }

    {
        int total = Hh * Nn * Nn;
        rpb_kernel<<<(total + 255) / 256, 256>>>(rel_table);
    }
    {
        dim3 grid(3 * Cc / 128, (M_TOT + 127) / 128);
        gemm_tf32<0><<<grid, 256, GEMM_SMEM>>>(x, qkv_w, q_bias, k_bias, v_bias, nullptr);
    }
    {
        dim3 grid((Nn + 63) / 64, Bb * Hh);
        attn_fused<<<grid, 128, ATTN_SMEM>>>();
    }
    {
        dim3 grid(Cc / 128, (M_TOT + 127) / 128);
        gemm_tf32<1><<<grid, 256, GEMM_SMEM>>>(nullptr, proj_w, proj_b, nullptr, nullptr, out);
    }
}

// round 4
// speedup vs baseline: 2.9506x; 1.1862x over previous
#include <cuda_runtime.h>
#include <cuda_bf16.h>
#include <cstddef>

// Problem constants
constexpr int Bb  = 64;
constexpr int Nn  = 197;
constexpr int Cc  = 768;
constexpr int Hh  = 12;
constexpr int Dd  = 64;
constexpr int M_TOT = Bb * Nn;        // 12608
constexpr int SLD  = 260;             // S row stride (floats) in fused kernel smem

// Scratch (device globals; allocation-free per harness rules)
__device__ float g_q[(size_t)Bb * Hh * Nn * Dd];       // [B,H,N,D], pre-scaled
__device__ float g_k[(size_t)Bb * Hh * Nn * Dd];
__device__ float g_v[(size_t)Bb * Hh * Nn * Dd];
__device__ float g_rpb[(size_t)Hh * Nn * Nn];          // [H, N, N]
__device__ float g_o[(size_t)Bb * Nn * Cc];            // [B, N, C]

// ---------------------------------------------------------------------------
// tf32 helpers
// ---------------------------------------------------------------------------
__device__ __forceinline__ unsigned f2tf(float f) {
    unsigned u;
    asm("cvt.rna.tf32.f32 %0, %1;" : "=r"(u) : "f"(f));
    return u;
}

__device__ __forceinline__ void mma_tf32(
    float& c0, float& c1, float& c2, float& c3,
    unsigned a0, unsigned a1, unsigned a2, unsigned a3,
    unsigned b0, unsigned b1)
{
    asm volatile(
        "mma.sync.aligned.m16n8k8.row.col.f32.tf32.tf32.f32 "
        "{%0,%1,%2,%3},{%4,%5,%6,%7},{%8,%9},{%0,%1,%2,%3};\n"
        : "+f"(c0), "+f"(c1), "+f"(c2), "+f"(c3)
        : "r"(a0), "r"(a1), "r"(a2), "r"(a3), "r"(b0), "r"(b1));
}

// ---------------------------------------------------------------------------
// Kernel 1: relative position bias gather
// ---------------------------------------------------------------------------
__global__ void rpb_kernel(const float* __restrict__ rel_table) {
    int tid = blockIdx.x * blockDim.x + threadIdx.x;
    const int total = Hh * Nn * Nn;
    if (tid >= total) return;
    int h = tid / (Nn * Nn);
    int r = tid % (Nn * Nn);
    int i = r / Nn, j = r % Nn;
    int idx;
    if (i == 0 && j == 0)      idx = 731;
    else if (i == 0)           idx = 729;
    else if (j == 0)           idx = 730;
    else {
        int a = i - 1, b = j - 1;
        int d0 = (a / 14 - b / 14) + 13;
        int d1 = (a % 14 - b % 14) + 13;
        idx = d0 * 27 + d1;
    }
    g_rpb[tid] = rel_table[idx * Hh + h];
}

// ---------------------------------------------------------------------------
// Kernels 2 & 4: tf32 GEMM C = A @ W^T (+bias), ping-pong smem (1 sync/iter)
// BM=128 BN=128 BK=32, 256 threads, 8 warps (4m x 2n), warp tile 32x64
// ---------------------------------------------------------------------------
template <int EPI>
__global__ __launch_bounds__(256) void gemm_tf32(
    const float* __restrict__ Ain, const float* __restrict__ W,
    const float* __restrict__ b0v, const float* __restrict__ b1v,
    const float* __restrict__ b2v, float* __restrict__ out)
{
    constexpr int K = 768, BM = 128, BK = 32;
    constexpr int TSTR = BK + 4;       // 36
    constexpr int BUFSZ = BM * TSTR;   // 4608 u32
    extern __shared__ unsigned gsm[];
    unsigned* Asb = gsm;               // [2][128][36]
    unsigned* Bsb = gsm + 2 * BUFSZ;   // [2][128][36]

    const float* A = (EPI == 0) ? Ain : (const float*)g_o;
    const int tid  = threadIdx.x;
    const int bm   = blockIdx.y * BM;
    const int bn   = blockIdx.x * BM;
    const int w    = tid >> 5, lane = tid & 31;
    const int wm   = w >> 1, wn = w & 1;
    const int m0w  = wm * 32, n0w = wn * 64;
    const int r    = lane >> 2, cg = lane & 3;

    float acc[2][8][4];
#pragma unroll
    for (int i = 0; i < 2; i++)
#pragma unroll
        for (int j = 0; j < 8; j++)
#pragma unroll
            for (int t = 0; t < 4; t++) acc[i][j][t] = 0.f;

    const int srow = tid >> 3;
    const int skc  = (tid & 7) * 4;

    float4 sa[4], sb[4];
#pragma unroll
    for (int i = 0; i < 4; i++) {
        int row = srow + i * 32;
        int gm = bm + row;
        sa[i] = (gm < M_TOT) ? *(const float4*)(A + (size_t)gm * K + skc)
                             : make_float4(0, 0, 0, 0);
        sb[i] = *(const float4*)(W + (size_t)(bn + row) * K + skc);
    }
#pragma unroll
    for (int i = 0; i < 4; i++) {
        int row = srow + i * 32;
        *(uint4*)&Asb[row * TSTR + skc] =
            make_uint4(f2tf(sa[i].x), f2tf(sa[i].y), f2tf(sa[i].z), f2tf(sa[i].w));
        *(uint4*)&Bsb[row * TSTR + skc] =
            make_uint4(f2tf(sb[i].x), f2tf(sb[i].y), f2tf(sb[i].z), f2tf(sb[i].w));
    }
    __syncthreads();

    int buf = 0;
    for (int kc0 = 0; kc0 < K; kc0 += BK) {
        const bool more = (kc0 + BK) < K;
        if (more) {
#pragma unroll
            for (int i = 0; i < 4; i++) {
                int row = srow + i * 32;
                int gm = bm + row;
                sa[i] = (gm < M_TOT)
                    ? *(const float4*)(A + (size_t)gm * K + kc0 + BK + skc)
                    : make_float4(0, 0, 0, 0);
                sb[i] = *(const float4*)(W + (size_t)(bn + row) * K + kc0 + BK + skc);
            }
        }

        const unsigned* As = Asb + buf * BUFSZ;
        const unsigned* Bs = Bsb + buf * BUFSZ;
#pragma unroll
        for (int ks = 0; ks < BK; ks += 8) {
            unsigned af[2][4], bf[8][2];
#pragma unroll
            for (int mt = 0; mt < 2; mt++) {
                int rb = m0w + mt * 16;
                af[mt][0] = As[(rb + r) * TSTR + ks + cg];
                af[mt][1] = As[(rb + r + 8) * TSTR + ks + cg];
                af[mt][2] = As[(rb + r) * TSTR + ks + cg + 4];
                af[mt][3] = As[(rb + r + 8) * TSTR + ks + cg + 4];
            }
#pragma unroll
            for (int nt = 0; nt < 8; nt++) {
                int nb = n0w + nt * 8;
                bf[nt][0] = Bs[(nb + r) * TSTR + ks + cg];
                bf[nt][1] = Bs[(nb + r) * TSTR + ks + cg + 4];
            }
#pragma unroll
            for (int mt = 0; mt < 2; mt++)
#pragma unroll
                for (int nt = 0; nt < 8; nt++)
                    mma_tf32(acc[mt][nt][0], acc[mt][nt][1],
                             acc[mt][nt][2], acc[mt][nt][3],
                             af[mt][0], af[mt][1], af[mt][2], af[mt][3],
                             bf[nt][0], bf[nt][1]);
        }

        if (more) {
            unsigned* An = Asb + (buf ^ 1) * BUFSZ;
            unsigned* Bn = Bsb + (buf ^ 1) * BUFSZ;
#pragma unroll
            for (int i = 0; i < 4; i++) {
                int row = srow + i * 32;
                *(uint4*)&An[row * TSTR + skc] =
                    make_uint4(f2tf(sa[i].x), f2tf(sa[i].y), f2tf(sa[i].z), f2tf(sa[i].w));
                *(uint4*)&Bn[row * TSTR + skc] =
                    make_uint4(f2tf(sb[i].x), f2tf(sb[i].y), f2tf(sb[i].z), f2tf(sb[i].w));
            }
            __syncthreads();
            buf ^= 1;
        }
    }

    // Epilogue (float2 stores)
#pragma unroll
    for (int mt = 0; mt < 2; mt++) {
        int mbase = bm + m0w + mt * 16;
#pragma unroll
        for (int nt = 0; nt < 8; nt++) {
            int nbase = bn + n0w + nt * 8 + 2 * cg;
#pragma unroll
            for (int half = 0; half < 2; half++) {
                int row = mbase + r + half * 8;
                if (row >= M_TOT) continue;
                float v0 = acc[mt][nt][half * 2 + 0];
                float v1 = acc[mt][nt][half * 2 + 1];
                if (EPI == 1) {
                    *(float2*)&out[(size_t)row * Cc + nbase] =
                        make_float2(v0 + b0v[nbase], v1 + b0v[nbase + 1]);
                } else {
                    int bI = row / Nn, n = row % Nn;
                    int which = nbase / Cc;      // uniform per CTA (128 | 768)
                    int cc = nbase % Cc;
                    int h = cc >> 6, d = cc & 63;
                    size_t off = (((size_t)bI * Hh + h) * Nn + n) * Dd + d;
                    if (which == 0)
                        *(float2*)&g_q[off] = make_float2((v0 + b0v[cc]) * 0.125f,
                                                          (v1 + b0v[cc + 1]) * 0.125f);
                    else if (which == 1)
                        *(float2*)&g_k[off] = make_float2(v0 + b1v[cc], v1 + b1v[cc + 1]);
                    else
                        *(float2*)&g_v[off] = make_float2(v0 + b2v[cc], v1 + b2v[cc + 1]);
                }
            }
        }
    }
}

// ---------------------------------------------------------------------------
// Kernel 3: fused attention per (bh, 64-row tile). 256 threads, 8 warps (2x4).
//   S = Q@K^T + rpb -> softmax (in-place tf32) -> O = P@V -> g_o
// smem: Qs[64][68] | KVs[64][72] (K staged stride 68, V stride 72) | Ss[64][260]
// total 102400 B
// ---------------------------------------------------------------------------
__global__ __launch_bounds__(256) void attn_fused() {
    extern __shared__ unsigned smemu[];
    unsigned* Qs  = smemu;                    // stride 68
    unsigned* KVs = smemu + 64 * 68;          // K: stride 68, V: stride 72
    float*    Ss  = (float*)(KVs + 64 * 72);  // stride SLD
    unsigned* Su  = (unsigned*)Ss;

    const int bh = blockIdx.y, h = bh % Hh, bI = bh / Hh;
    const int m0 = blockIdx.x * 64;
    const int tid = threadIdx.x, lane = tid & 31, w = tid >> 5;
    const int wm = w >> 2;          // 0..1 : 32 rows
    const int wn = w & 3;           // 0..3 : 16 cols
    const int r = lane >> 2, cg = lane & 3;
    const float* qb = g_q + (size_t)bh * Nn * Dd;
    const float* kb = g_k + (size_t)bh * Nn * Dd;
    const float* vb = g_v + (size_t)bh * Nn * Dd;

    // ---- load Q tile (tf32), stride 68 ----
#pragma unroll
    for (int i = 0; i < 4; i++) {
        int s = tid + i * 256;
        int row = s >> 4, kc = (s & 15) * 4;
        float4 qv = (m0 + row < Nn)
            ? *(const float4*)(qb + (size_t)(m0 + row) * Dd + kc)
            : make_float4(0, 0, 0, 0);
        *(uint4*)&Qs[row * 68 + kc] =
            make_uint4(f2tf(qv.x), f2tf(qv.y), f2tf(qv.z), f2tf(qv.w));
    }

    // ---- scores: 4 K-tiles of 64 cols ----
    for (int nt0 = 0; nt0 < 4; nt0++) {
        const int n0 = nt0 * 64;
        __syncthreads();   // KVs free (prev chunk readers done) / Qs visible
#pragma unroll
        for (int i = 0; i < 4; i++) {
            int s = tid + i * 256;
            int row = s >> 4, kc = (s & 15) * 4;
            float4 kv = (n0 + row < Nn)
                ? *(const float4*)(kb + (size_t)(n0 + row) * Dd + kc)
                : make_float4(0, 0, 0, 0);
            *(uint4*)&KVs[row * 68 + kc] =
                make_uint4(f2tf(kv.x), f2tf(kv.y), f2tf(kv.z), f2tf(kv.w));
        }
        __syncthreads();

        float acc[2][2][4];
#pragma unroll
        for (int i = 0; i < 2; i++)
#pragma unroll
            for (int j = 0; j < 2; j++)
#pragma unroll
                for (int t = 0; t < 4; t++) acc[i][j][t] = 0.f;

#pragma unroll
        for (int ks = 0; ks < 64; ks += 8) {
            unsigned af[2][4], bf[2][2];
#pragma unroll
            for (int mt = 0; mt < 2; mt++) {
                int rb = wm * 32 + mt * 16;
                af[mt][0] = Qs[(rb + r) * 68 + ks + cg];
                af[mt][1] = Qs[(rb + r + 8) * 68 + ks + cg];
                af[mt][2] = Qs[(rb + r) * 68 + ks + cg + 4];
                af[mt][3] = Qs[(rb + r + 8) * 68 + ks + cg + 4];
            }
#pragma unroll
            for (int nt = 0; nt < 2; nt++) {
                int nb = wn * 16 + nt * 8;
                bf[nt][0] = KVs[(nb + r) * 68 + ks + cg];
                bf[nt][1] = KVs[(nb + r) * 68 + ks + cg + 4];
            }
#pragma unroll
            for (int mt = 0; mt < 2; mt++)
#pragma unroll
                for (int nt = 0; nt < 2; nt++)
                    mma_tf32(acc[mt][nt][0], acc[mt][nt][1],
                             acc[mt][nt][2], acc[mt][nt][3],
                             af[mt][0], af[mt][1], af[mt][2], af[mt][3],
                             bf[nt][0], bf[nt][1]);
        }

        // write S tile (+rpb); invalid cells -> 0
#pragma unroll
        for (int mt = 0; mt < 2; mt++) {
            int mlb = wm * 32 + mt * 16;
#pragma unroll
            for (int nt = 0; nt < 2; nt++) {
                int nl = wn * 16 + nt * 8 + 2 * cg;
#pragma unroll
                for (int half = 0; half < 2; half++) {
                    int ml = mlb + r + half * 8;
                    int mg = m0 + ml;
                    float v0 = 0.f, v1 = 0.f;
                    if (mg < Nn) {
                        int ng0 = n0 + nl, ng1 = ng0 + 1;
                        const float* rp = g_rpb + ((size_t)h * Nn + mg) * Nn;
                        if (ng0 < Nn) v0 = acc[mt][nt][half * 2 + 0] + rp[ng0];
                        if (ng1 < Nn) v1 = acc[mt][nt][half * 2 + 1] + rp[ng1];
                    }
                    *(float2*)&Ss[ml * SLD + n0 + nl] = make_float2(v0, v1);
                }
            }
        }
    }
    __syncthreads();

    // ---- softmax: one warp per row, 8 rows per warp ----
    for (int row = w; row < 64; row += 8) {
        float* sr = Ss + row * SLD;
        float mx = -1e30f;
        for (int j = lane; j < Nn; j += 32) mx = fmaxf(mx, sr[j]);
#pragma unroll
        for (int o = 16; o; o >>= 1) mx = fmaxf(mx, __shfl_xor_sync(0xffffffffu, mx, o));
        float s = 0.f;
        for (int j = lane; j < Nn; j += 32) {
            float e = __expf(sr[j] - mx);
            sr[j] = e;
            s += e;
        }
#pragma unroll
        for (int o = 16; o; o >>= 1) s += __shfl_xor_sync(0xffffffffu, s, o);
        float inv = 1.f / s;
        for (int j = lane; j < Nn; j += 32)
            ((unsigned*)sr)[j] = f2tf(sr[j] * inv);
        // pad cols [197,256) hold 0.0f == tf32 zero
    }

    // ---- PV: O = P @ V over 4 chunks of 64 ----
    float accO[2][2][4];
#pragma unroll
    for (int i = 0; i < 2; i++)
#pragma unroll
        for (int j = 0; j < 2; j++)
#pragma unroll
            for (int t = 0; t < 4; t++) accO[i][j][t] = 0.f;

    for (int k0 = 0; k0 < 256; k0 += 64) {
        __syncthreads();   // KVs free (prev readers done) / softmax done (1st iter)
#pragma unroll
        for (int i = 0; i < 4; i++) {
            int s = tid + i * 256;
            int tok = s >> 4, dc = (s & 15) * 4;
            int kk = k0 + tok;
            float4 vv = (kk < Nn)
                ? *(const float4*)(vb + (size_t)kk * Dd + dc)
                : make_float4(0, 0, 0, 0);
            *(uint4*)&KVs[tok * 72 + dc] =
                make_uint4(f2tf(vv.x), f2tf(vv.y), f2tf(vv.z), f2tf(vv.w));
        }
        __syncthreads();

#pragma unroll
        for (int ks = 0; ks < 64; ks += 8) {
            unsigned af[2][4], bf[2][2];
#pragma unroll
            for (int mt = 0; mt < 2; mt++) {
                int rb = wm * 32 + mt * 16;
                af[mt][0] = Su[(rb + r) * SLD + k0 + ks + cg];
                af[mt][1] = Su[(rb + r + 8) * SLD + k0 + ks + cg];
                af[mt][2] = Su[(rb + r) * SLD + k0 + ks + cg + 4];
                af[mt][3] = Su[(rb + r + 8) * SLD + k0 + ks + cg + 4];
            }
#pragma unroll
            for (int nt = 0; nt < 2; nt++) {
                int nb = wn * 16 + nt * 8;
                bf[nt][0] = KVs[(ks + cg) * 72 + nb + r];
                bf[nt][1] = KVs[(ks + cg + 4) * 72 + nb + r];
            }
#pragma unroll
            for (int mt = 0; mt < 2; mt++)
#pragma unroll
                for (int nt = 0; nt < 2; nt++)
                    mma_tf32(accO[mt][nt][0], accO[mt][nt][1],
                             accO[mt][nt][2], accO[mt][nt][3],
                             af[mt][0], af[mt][1], af[mt][2], af[mt][3],
                             bf[nt][0], bf[nt][1]);
        }
    }

    // ---- store O tile to g_o [B,N,C] ----
#pragma unroll
    for (int mt = 0; mt < 2; mt++) {
        int mbase = m0 + wm * 32 + mt * 16;
#pragma unroll
        for (int nt = 0; nt < 2; nt++) {
            int nb = wn * 16 + nt * 8 + 2 * cg;
#pragma unroll
            for (int half = 0; half < 2; half++) {
                int m = mbase + r + half * 8;
                if (m >= Nn) continue;
                size_t o = ((size_t)bI * Nn + m) * Cc + h * Dd + nb;
                *(float2*)&g_o[o] = make_float2(accO[mt][nt][half * 2 + 0],
                                                accO[mt][nt][half * 2 + 1]);
            }
        }
    }
}

// ---------------------------------------------------------------------------
extern "C" void kernel_launch(void* const* d_in, const int* in_sizes, int n_in,
                              void* d_out, int out_size)
{
    const float* x         = (const float*)d_in[0];
    const float* qkv_w     = (const float*)d_in[1];
    const float* q_bias    = (const float*)d_in[2];
    const float* k_bias    = (const float*)d_in[3];
    const float* v_bias    = (const float*)d_in[4];
    const float* rel_table = (const float*)d_in[5];
    const float* proj_w    = (const float*)d_in[6];
    const float* proj_b    = (const float*)d_in[7];
    float* out = (float*)d_out;

    constexpr int GEMM_SMEM = 4 * 128 * 36 * 4;                       // 73728
    constexpr int ATTN_SMEM = (64 * 68 + 64 * 72) * 4 + 64 * SLD * 4; // 102400

    static bool attr_done = false;
    if (!attr_done) {
        cudaFuncSetAttribute(gemm_tf32<0>, cudaFuncAttributeMaxDynamicSharedMemorySize, GEMM_SMEM);
        cudaFuncSetAttribute(gemm_tf32<1>, cudaFuncAttributeMaxDynamicSharedMemorySize, GEMM_SMEM);
        cudaFuncSetAttribute(attn_fused,   cudaFuncAttributeMaxDynamicSharedMemorySize, ATTN_SMEM);
        attr_done = true;
    }

    {
        int total = Hh * Nn * Nn;
        rpb_kernel<<<(total + 255) / 256, 256>>>(rel_table);
    }
    {
        dim3 grid(3 * Cc / 128, (M_TOT + 127) / 128);
        gemm_tf32<0><<<grid, 256, GEMM_SMEM>>>(x, qkv_w, q_bias, k_bias, v_bias, nullptr);
    }
    {
        dim3 grid((Nn + 63) / 64, Bb * Hh);
        attn_fused<<<grid, 256, ATTN_SMEM>>>();
    }
    {
        dim3 grid(Cc / 128, (M_TOT + 127) / 128);
        gemm_tf32<1><<<grid, 256, GEMM_SMEM>>>(nullptr, proj_w, proj_b, nullptr, nullptr, out);
    }
}

// round 5
// speedup vs baseline: 3.9336x; 1.3332x over previous
#include <cuda_runtime.h>
#include <cuda_fp16.h>
#include <cstddef>

// Problem constants
constexpr int Bb  = 64;
constexpr int Nn  = 197;
constexpr int Cc  = 768;
constexpr int Hh  = 12;
constexpr int Dd  = 64;
constexpr int M_TOT = Bb * Nn;        // 12608
constexpr int SLD  = 260;             // S row stride (floats) in fused kernel

// Scratch (device globals) — all fp16 now
__device__ __half g_q[(size_t)Bb * Hh * Nn * Dd];
__device__ __half g_k[(size_t)Bb * Hh * Nn * Dd];
__device__ __half g_v[(size_t)Bb * Hh * Nn * Dd];
__device__ float  g_rpb[(size_t)Hh * Nn * Nn];
__device__ __half g_o[(size_t)Bb * Nn * Cc];

// ---------------------------------------------------------------------------
// helpers
// ---------------------------------------------------------------------------
__device__ __forceinline__ unsigned pack2(float x, float y) {
    __half2 h = __float22half2_rn(make_float2(x, y));
    return *reinterpret_cast<unsigned*>(&h);
}

__device__ __forceinline__ void mma_f16(
    float& c0, float& c1, float& c2, float& c3,
    unsigned a0, unsigned a1, unsigned a2, unsigned a3,
    unsigned b0, unsigned b1)
{
    asm volatile(
        "mma.sync.aligned.m16n8k16.row.col.f32.f16.f16.f32 "
        "{%0,%1,%2,%3},{%4,%5,%6,%7},{%8,%9},{%0,%1,%2,%3};\n"
        : "+f"(c0), "+f"(c1), "+f"(c2), "+f"(c3)
        : "r"(a0), "r"(a1), "r"(a2), "r"(a3), "r"(b0), "r"(b1));
}

// ---------------------------------------------------------------------------
// Kernel 1: relative position bias gather
// ---------------------------------------------------------------------------
__global__ void rpb_kernel(const float* __restrict__ rel_table) {
    int tid = blockIdx.x * blockDim.x + threadIdx.x;
    const int total = Hh * Nn * Nn;
    if (tid >= total) return;
    int h = tid / (Nn * Nn);
    int r = tid % (Nn * Nn);
    int i = r / Nn, j = r % Nn;
    int idx;
    if (i == 0 && j == 0)      idx = 731;
    else if (i == 0)           idx = 729;
    else if (j == 0)           idx = 730;
    else {
        int a = i - 1, b = j - 1;
        int d0 = (a / 14 - b / 14) + 13;
        int d1 = (a % 14 - b % 14) + 13;
        idx = d0 * 27 + d1;
    }
    g_rpb[tid] = rel_table[idx * Hh + h];
}

// ---------------------------------------------------------------------------
// Kernels 2 & 4: fp16 GEMM  C = A @ W^T (+bias), ping-pong smem
// BM=128 BN=128 BK=32 (k-elements), 256 threads, 8 warps (4m x 2n), warp 32x64
// Smem rows: 16 half2 + 4 pad = stride 20 u32. 2 k16-steps per chunk.
// EPI==0: A = x (float), scatter q/k/v as fp16 (q pre-scaled)
// EPI==1: A = g_o (fp16), out = A@W^T + proj_b (fp32)
// ---------------------------------------------------------------------------
template <int EPI>
__global__ __launch_bounds__(256) void gemm_f16(
    const float* __restrict__ Af, const float* __restrict__ W,
    const float* __restrict__ b0v, const float* __restrict__ b1v,
    const float* __restrict__ b2v, float* __restrict__ out)
{
    constexpr int K = 768, BM = 128;
    constexpr int TSTR = 20;           // u32 per row (16 data + 4 pad)
    constexpr int BUFSZ = BM * TSTR;   // 2560 u32
    extern __shared__ unsigned gsm[];
    unsigned* Asb = gsm;               // [2][128][20]
    unsigned* Bsb = gsm + 2 * BUFSZ;

    const __half* Ah = (const __half*)g_o;   // used when EPI==1
    const int tid  = threadIdx.x;
    const int bm   = blockIdx.y * BM;
    const int bn   = blockIdx.x * BM;
    const int w    = tid >> 5, lane = tid & 31;
    const int wm   = w >> 1, wn = w & 1;
    const int m0w  = wm * 32, n0w = wn * 64;
    const int r    = lane >> 2, cg = lane & 3;

    float acc[2][8][4];
#pragma unroll
    for (int i = 0; i < 2; i++)
#pragma unroll
        for (int j = 0; j < 8; j++)
#pragma unroll
            for (int t = 0; t < 4; t++) acc[i][j][t] = 0.f;

    const int srow = tid >> 3;          // +32*i -> 128 rows
    const int skc  = (tid & 7) * 4;     // k-element (half/float) offset

    uint2 sa2[4], sb2[4];
    auto loadA = [&](int i, int kbase) {
        int row = srow + i * 32;
        int gm = bm + row;
        if (EPI == 0) {
            float4 a = (gm < M_TOT)
                ? *(const float4*)(Af + (size_t)gm * K + kbase + skc)
                : make_float4(0, 0, 0, 0);
            sa2[i] = make_uint2(pack2(a.x, a.y), pack2(a.z, a.w));
        } else {
            sa2[i] = (gm < M_TOT)
                ? *(const uint2*)(Ah + (size_t)gm * K + kbase + skc)
                : make_uint2(0, 0);
        }
    };
    auto loadB = [&](int i, int kbase) {
        int row = srow + i * 32;
        float4 b = *(const float4*)(W + (size_t)(bn + row) * K + kbase + skc);
        sb2[i] = make_uint2(pack2(b.x, b.y), pack2(b.z, b.w));
    };

#pragma unroll
    for (int i = 0; i < 4; i++) { loadA(i, 0); loadB(i, 0); }
#pragma unroll
    for (int i = 0; i < 4; i++) {
        int row = srow + i * 32;
        *(uint2*)&Asb[row * TSTR + (skc >> 1)] = sa2[i];
        *(uint2*)&Bsb[row * TSTR + (skc >> 1)] = sb2[i];
    }
    __syncthreads();

    int buf = 0;
    for (int kc0 = 0; kc0 < K; kc0 += 32) {
        const bool more = (kc0 + 32) < K;
        if (more) {
#pragma unroll
            for (int i = 0; i < 4; i++) { loadA(i, kc0 + 32); loadB(i, kc0 + 32); }
        }

        const unsigned* As = Asb + buf * BUFSZ;
        const unsigned* Bs = Bsb + buf * BUFSZ;
#pragma unroll
        for (int ks = 0; ks < 2; ks++) {
            const int kb = ks * 8;
            unsigned af[2][4], bf[8][2];
#pragma unroll
            for (int mt = 0; mt < 2; mt++) {
                int rb = m0w + mt * 16;
                af[mt][0] = As[(rb + r) * TSTR + kb + cg];
                af[mt][1] = As[(rb + r + 8) * TSTR + kb + cg];
                af[mt][2] = As[(rb + r) * TSTR + kb + cg + 4];
                af[mt][3] = As[(rb + r + 8) * TSTR + kb + cg + 4];
            }
#pragma unroll
            for (int nt = 0; nt < 8; nt++) {
                int nb = n0w + nt * 8;
                bf[nt][0] = Bs[(nb + r) * TSTR + kb + cg];
                bf[nt][1] = Bs[(nb + r) * TSTR + kb + cg + 4];
            }
#pragma unroll
            for (int mt = 0; mt < 2; mt++)
#pragma unroll
                for (int nt = 0; nt < 8; nt++)
                    mma_f16(acc[mt][nt][0], acc[mt][nt][1],
                            acc[mt][nt][2], acc[mt][nt][3],
                            af[mt][0], af[mt][1], af[mt][2], af[mt][3],
                            bf[nt][0], bf[nt][1]);
        }

        if (more) {
            unsigned* An = Asb + (buf ^ 1) * BUFSZ;
            unsigned* Bn = Bsb + (buf ^ 1) * BUFSZ;
#pragma unroll
            for (int i = 0; i < 4; i++) {
                int row = srow + i * 32;
                *(uint2*)&An[row * TSTR + (skc >> 1)] = sa2[i];
                *(uint2*)&Bn[row * TSTR + (skc >> 1)] = sb2[i];
            }
            __syncthreads();
            buf ^= 1;
        }
    }

    // Epilogue
#pragma unroll
    for (int mt = 0; mt < 2; mt++) {
        int mbase = bm + m0w + mt * 16;
#pragma unroll
        for (int nt = 0; nt < 8; nt++) {
            int nbase = bn + n0w + nt * 8 + 2 * cg;
#pragma unroll
            for (int half = 0; half < 2; half++) {
                int row = mbase + r + half * 8;
                if (row >= M_TOT) continue;
                float v0 = acc[mt][nt][half * 2 + 0];
                float v1 = acc[mt][nt][half * 2 + 1];
                if (EPI == 1) {
                    *(float2*)&out[(size_t)row * Cc + nbase] =
                        make_float2(v0 + b0v[nbase], v1 + b0v[nbase + 1]);
                } else {
                    int bI = row / Nn, n = row % Nn;
                    int which = nbase / Cc;      // uniform per CTA
                    int cc = nbase % Cc;
                    int h = cc >> 6, d = cc & 63;
                    size_t off = (((size_t)bI * Hh + h) * Nn + n) * Dd + d;
                    if (which == 0)
                        *(unsigned*)&g_q[off] = pack2((v0 + b0v[cc]) * 0.125f,
                                                      (v1 + b0v[cc + 1]) * 0.125f);
                    else if (which == 1)
                        *(unsigned*)&g_k[off] = pack2(v0 + b1v[cc], v1 + b1v[cc + 1]);
                    else
                        *(unsigned*)&g_v[off] = pack2(v0 + b2v[cc], v1 + b2v[cc + 1]);
                }
            }
        }
    }
}

// ---------------------------------------------------------------------------
// Kernel 3: fused attention, fp16 mma. 256 threads, 8 warps (2m x 4n).
// smem (u32 units): Qs[64][36] | KVs[64][36] | Ss[64][260] f32
//   (probs packed in place over the low 128 u32 of each Ss row)
// total 84992 B, 2 CTA/SM
// ---------------------------------------------------------------------------
__global__ __launch_bounds__(256) void attn_fused() {
    extern __shared__ unsigned smemu[];
    unsigned* Qs  = smemu;                    // stride 36 (half2 units)
    unsigned* KVs = smemu + 64 * 36;          // K rows / V transposed
    float*    Ss  = (float*)(smemu + 2 * 64 * 36);
    unsigned* Su  = smemu + 2 * 64 * 36;

    const int bh = blockIdx.y, h = bh % Hh, bI = bh / Hh;
    const int m0 = blockIdx.x * 64;
    const int tid = threadIdx.x, lane = tid & 31, w = tid >> 5;
    const int wm = w >> 2;          // 0..1
    const int wn = w & 3;           // 0..3
    const int r = lane >> 2, cg = lane & 3;
    const __half* qb = g_q + (size_t)bh * Nn * Dd;
    const __half* kb = g_k + (size_t)bh * Nn * Dd;
    const __half* vb = g_v + (size_t)bh * Nn * Dd;

    // ---- load Q tile (64x64 halves = 64x32 u32, stride 36) ----
#pragma unroll
    for (int i = 0; i < 2; i++) {
        int s = tid + i * 256;
        int row = s >> 3, c4 = (s & 7);
        uint4 v = (m0 + row < Nn)
            ? ((const uint4*)(qb + (size_t)(m0 + row) * Dd))[c4]
            : make_uint4(0, 0, 0, 0);
        *(uint4*)&Qs[row * 36 + c4 * 4] = v;
    }

    // ---- scores: 4 K-tiles of 64 tokens ----
    for (int nt0 = 0; nt0 < 4; nt0++) {
        const int n0 = nt0 * 64;
        __syncthreads();
#pragma unroll
        for (int i = 0; i < 2; i++) {
            int s = tid + i * 256;
            int row = s >> 3, c4 = (s & 7);
            uint4 v = (n0 + row < Nn)
                ? ((const uint4*)(kb + (size_t)(n0 + row) * Dd))[c4]
                : make_uint4(0, 0, 0, 0);
            *(uint4*)&KVs[row * 36 + c4 * 4] = v;
        }
        __syncthreads();

        float acc[2][2][4];
#pragma unroll
        for (int i = 0; i < 2; i++)
#pragma unroll
            for (int j = 0; j < 2; j++)
#pragma unroll
                for (int t = 0; t < 4; t++) acc[i][j][t] = 0.f;

#pragma unroll
        for (int ks = 0; ks < 4; ks++) {        // 4 x k16 = Dd 64
            const int kbu = ks * 8;
            unsigned af[2][4], bf[2][2];
#pragma unroll
            for (int mt = 0; mt < 2; mt++) {
                int rb = wm * 32 + mt * 16;
                af[mt][0] = Qs[(rb + r) * 36 + kbu + cg];
                af[mt][1] = Qs[(rb + r + 8) * 36 + kbu + cg];
                af[mt][2] = Qs[(rb + r) * 36 + kbu + cg + 4];
                af[mt][3] = Qs[(rb + r + 8) * 36 + kbu + cg + 4];
            }
#pragma unroll
            for (int nt = 0; nt < 2; nt++) {
                int nb = wn * 16 + nt * 8;
                bf[nt][0] = KVs[(nb + r) * 36 + kbu + cg];
                bf[nt][1] = KVs[(nb + r) * 36 + kbu + cg + 4];
            }
#pragma unroll
            for (int mt = 0; mt < 2; mt++)
#pragma unroll
                for (int nt = 0; nt < 2; nt++)
                    mma_f16(acc[mt][nt][0], acc[mt][nt][1],
                            acc[mt][nt][2], acc[mt][nt][3],
                            af[mt][0], af[mt][1], af[mt][2], af[mt][3],
                            bf[nt][0], bf[nt][1]);
        }

        // write S tile (+rpb) fp32; out-of-range cells -> 0
#pragma unroll
        for (int mt = 0; mt < 2; mt++) {
            int mlb = wm * 32 + mt * 16;
#pragma unroll
            for (int nt = 0; nt < 2; nt++) {
                int nl = wn * 16 + nt * 8 + 2 * cg;
#pragma unroll
                for (int half = 0; half < 2; half++) {
                    int ml = mlb + r + half * 8;
                    int mg = m0 + ml;
                    float v0 = 0.f, v1 = 0.f;
                    if (mg < Nn) {
                        int ng0 = n0 + nl, ng1 = ng0 + 1;
                        const float* rp = g_rpb + ((size_t)h * Nn + mg) * Nn;
                        if (ng0 < Nn) v0 = acc[mt][nt][half * 2 + 0] + rp[ng0];
                        if (ng1 < Nn) v1 = acc[mt][nt][half * 2 + 1] + rp[ng1];
                    }
                    *(float2*)&Ss[ml * SLD + n0 + nl] = make_float2(v0, v1);
                }
            }
        }
    }
    __syncthreads();

    // ---- softmax per row (one warp per row, 8 rows/warp), pack to half2 ----
    for (int row = w; row < 64; row += 8) {
        float* sr = Ss + row * SLD;
        float mx = -1e30f;
        for (int j = lane; j < Nn; j += 32) mx = fmaxf(mx, sr[j]);
#pragma unroll
        for (int o = 16; o; o >>= 1) mx = fmaxf(mx, __shfl_xor_sync(0xffffffffu, mx, o));
        float s = 0.f;
        for (int j = lane; j < Nn; j += 32) {
            float e = __expf(sr[j] - mx);
            sr[j] = e;
            s += e;
        }
#pragma unroll
        for (int o = 16; o; o >>= 1) s += __shfl_xor_sync(0xffffffffu, s, o);
        float inv = 1.f / s;
        // pack pairs in place over the low 128 u32 of the row
        unsigned* pu = (unsigned*)sr;
#pragma unroll
        for (int j4 = 0; j4 < 4; j4++) {
            int j = lane + j4 * 32;                 // 0..127 (token pair index)
            float2 p = *(float2*)&sr[2 * j];        // tokens 2j, 2j+1 (pads = 0)
            __syncwarp();
            pu[j] = pack2(p.x * inv, p.y * inv);
        }
    }

    // ---- PV: O = P @ V over 4 chunks of 64 tokens ----
    float accO[2][2][4];
#pragma unroll
    for (int i = 0; i < 2; i++)
#pragma unroll
        for (int j = 0; j < 2; j++)
#pragma unroll
            for (int t = 0; t < 4; t++) accO[i][j][t] = 0.f;

    for (int c = 0; c < 4; c++) {
        const int k0 = c * 64;
        __syncthreads();
        // stage V transposed: KVs[d][tokpair] = half2(V[2tp], V[2tp+1]) at dim d
#pragma unroll
        for (int i = 0; i < 2; i++) {
            int s = tid + i * 256;
            int tp = s & 31, dc = (s >> 5) * 4;    // tokpair 0..31, dims dc..dc+3
            int t0 = k0 + 2 * tp;
            uint2 h0 = (t0 < Nn)     ? *(const uint2*)(vb + (size_t)t0 * Dd + dc)
                                     : make_uint2(0, 0);
            uint2 h1 = (t0 + 1 < Nn) ? *(const uint2*)(vb + (size_t)(t0 + 1) * Dd + dc)
                                     : make_uint2(0, 0);
            const __half* a = (const __half*)&h0;
            const __half* b = (const __half*)&h1;
#pragma unroll
            for (int e = 0; e < 4; e++) {
                __half2 hv = __halves2half2(a[e], b[e]);
                KVs[(dc + e) * 36 + tp] = *reinterpret_cast<unsigned*>(&hv);
            }
        }
        __syncthreads();

#pragma unroll
        for (int ks = 0; ks < 4; ks++) {           // 4 x k16 per 64-token chunk
            const int kbu = c * 32 + ks * 8;       // u32 offset into packed P row
            unsigned af[2][4], bf[2][2];
#pragma unroll
            for (int mt = 0; mt < 2; mt++) {
                int rb = wm * 32 + mt * 16;
                af[mt][0] = Su[(rb + r) * SLD + kbu + cg];
                af[mt][1] = Su[(rb + r + 8) * SLD + kbu + cg];
                af[mt][2] = Su[(rb + r) * SLD + kbu + cg + 4];
                af[mt][3] = Su[(rb + r + 8) * SLD + kbu + cg + 4];
            }
#pragma unroll
            for (int nt = 0; nt < 2; nt++) {
                int nb = wn * 16 + nt * 8;
                bf[nt][0] = KVs[(nb + r) * 36 + ks * 8 + cg];
                bf[nt][1] = KVs[(nb + r) * 36 + ks * 8 + cg + 4];
            }
#pragma unroll
            for (int mt = 0; mt < 2; mt++)
#pragma unroll
                for (int nt = 0; nt < 2; nt++)
                    mma_f16(accO[mt][nt][0], accO[mt][nt][1],
                            accO[mt][nt][2], accO[mt][nt][3],
                            af[mt][0], af[mt][1], af[mt][2], af[mt][3],
                            bf[nt][0], bf[nt][1]);
        }
    }

    // ---- store O tile (fp16) to g_o [B,N,C] ----
#pragma unroll
    for (int mt = 0; mt < 2; mt++) {
        int mbase = m0 + wm * 32 + mt * 16;
#pragma unroll
        for (int nt = 0; nt < 2; nt++) {
            int nb = wn * 16 + nt * 8 + 2 * cg;
#pragma unroll
            for (int half = 0; half < 2; half++) {
                int m = mbase + r + half * 8;
                if (m >= Nn) continue;
                size_t o = ((size_t)bI * Nn + m) * Cc + h * Dd + nb;
                *(unsigned*)&g_o[o] = pack2(accO[mt][nt][half * 2 + 0],
                                            accO[mt][nt][half * 2 + 1]);
            }
        }
    }
}

// ---------------------------------------------------------------------------
extern "C" void kernel_launch(void* const* d_in, const int* in_sizes, int n_in,
                              void* d_out, int out_size)
{
    const float* x         = (const float*)d_in[0];
    const float* qkv_w     = (const float*)d_in[1];
    const float* q_bias    = (const float*)d_in[2];
    const float* k_bias    = (const float*)d_in[3];
    const float* v_bias    = (const float*)d_in[4];
    const float* rel_table = (const float*)d_in[5];
    const float* proj_w    = (const float*)d_in[6];
    const float* proj_b    = (const float*)d_in[7];
    float* out = (float*)d_out;

    constexpr int GEMM_SMEM = 4 * 128 * 20 * 4;                   // 40960
    constexpr int ATTN_SMEM = (2 * 64 * 36 + 64 * SLD) * 4;       // 84992

    static bool attr_done = false;
    if (!attr_done) {
        cudaFuncSetAttribute(gemm_f16<0>, cudaFuncAttributeMaxDynamicSharedMemorySize, GEMM_SMEM);
        cudaFuncSetAttribute(gemm_f16<1>, cudaFuncAttributeMaxDynamicSharedMemorySize, GEMM_SMEM);
        cudaFuncSetAttribute(attn_fused,  cudaFuncAttributeMaxDynamicSharedMemorySize, ATTN_SMEM);
        attr_done = true;
    }

    {
        int total = Hh * Nn * Nn;
        rpb_kernel<<<(total + 255) / 256, 256>>>(rel_table);
    }
    {
        dim3 grid(3 * Cc / 128, (M_TOT + 127) / 128);
        gemm_f16<0><<<grid, 256, GEMM_SMEM>>>(x, qkv_w, q_bias, k_bias, v_bias, nullptr);
    }
    {
        dim3 grid((Nn + 63) / 64, Bb * Hh);
        attn_fused<<<grid, 256, ATTN_SMEM>>>();
    }
    {
        dim3 grid(Cc / 128, (M_TOT + 127) / 128);
        gemm_f16<1><<<grid, 256, GEMM_SMEM>>>(nullptr, proj_w, proj_b, nullptr, nullptr, out);
    }
}

// round 6
// speedup vs baseline: 4.1811x; 1.0629x over previous
#include <cuda_runtime.h>
#include <cuda_fp16.h>
#include <cstddef>

// Problem constants
constexpr int Bb  = 64;
constexpr int Nn  = 197;
constexpr int Cc  = 768;
constexpr int Hh  = 12;
constexpr int Dd  = 64;
constexpr int M_TOT = Bb * Nn;        // 12608
constexpr int SLD  = 260;             // S row stride (floats) in fused kernel

// Scratch (device globals) — fp16
__device__ __half g_q[(size_t)Bb * Hh * Nn * Dd];
__device__ __half g_k[(size_t)Bb * Hh * Nn * Dd];
__device__ __half g_v[(size_t)Bb * Hh * Nn * Dd];
__device__ float  g_rpb[(size_t)Hh * Nn * Nn];
__device__ __half g_o[(size_t)Bb * Nn * Cc];

// ---------------------------------------------------------------------------
// helpers
// ---------------------------------------------------------------------------
__device__ __forceinline__ unsigned pack2(float x, float y) {
    __half2 h = __float22half2_rn(make_float2(x, y));
    return *reinterpret_cast<unsigned*>(&h);
}

__device__ __forceinline__ void mma_f16(
    float& c0, float& c1, float& c2, float& c3,
    unsigned a0, unsigned a1, unsigned a2, unsigned a3,
    unsigned b0, unsigned b1)
{
    asm volatile(
        "mma.sync.aligned.m16n8k16.row.col.f32.f16.f16.f32 "
        "{%0,%1,%2,%3},{%4,%5,%6,%7},{%8,%9},{%0,%1,%2,%3};\n"
        : "+f"(c0), "+f"(c1), "+f"(c2), "+f"(c3)
        : "r"(a0), "r"(a1), "r"(a2), "r"(a3), "r"(b0), "r"(b1));
}

__device__ __forceinline__ void ldsm_x4(
    unsigned& r0, unsigned& r1, unsigned& r2, unsigned& r3, unsigned addr)
{
    asm volatile("ldmatrix.sync.aligned.m8n8.x4.shared.b16 {%0,%1,%2,%3}, [%4];"
                 : "=r"(r0), "=r"(r1), "=r"(r2), "=r"(r3) : "r"(addr));
}

// ---------------------------------------------------------------------------
// Kernel 1: relative position bias gather
// ---------------------------------------------------------------------------
__global__ void rpb_kernel(const float* __restrict__ rel_table) {
    int tid = blockIdx.x * blockDim.x + threadIdx.x;
    const int total = Hh * Nn * Nn;
    if (tid >= total) return;
    int h = tid / (Nn * Nn);
    int r = tid % (Nn * Nn);
    int i = r / Nn, j = r % Nn;
    int idx;
    if (i == 0 && j == 0)      idx = 731;
    else if (i == 0)           idx = 729;
    else if (j == 0)           idx = 730;
    else {
        int a = i - 1, b = j - 1;
        int d0 = (a / 14 - b / 14) + 13;
        int d1 = (a % 14 - b % 14) + 13;
        idx = d0 * 27 + d1;
    }
    g_rpb[tid] = rel_table[idx * Hh + h];
}

// ---------------------------------------------------------------------------
// Kernels 2 & 4: fp16 GEMM  C = A @ W^T (+bias), ping-pong smem + ldmatrix
// BM=128 BN=128 BK=32, 256 threads, 8 warps (4m x 2n), warp 32x64
// ---------------------------------------------------------------------------
template <int EPI>
__global__ __launch_bounds__(256) void gemm_f16(
    const float* __restrict__ Af, const float* __restrict__ W,
    const float* __restrict__ b0v, const float* __restrict__ b1v,
    const float* __restrict__ b2v, float* __restrict__ out)
{
    constexpr int K = 768, BM = 128;
    constexpr int TSTR = 20;           // u32 per row (16 data + 4 pad)
    constexpr int BUFSZ = BM * TSTR;   // u32
    extern __shared__ unsigned gsm[];
    unsigned* Asb = gsm;               // [2][128][20]
    unsigned* Bsb = gsm + 2 * BUFSZ;

    const unsigned as_base = (unsigned)__cvta_generic_to_shared(Asb);
    const unsigned bs_base = (unsigned)__cvta_generic_to_shared(Bsb);

    const __half* Ah = (const __half*)g_o;   // EPI==1
    const int tid  = threadIdx.x;
    const int bm   = blockIdx.y * BM;
    const int bn   = blockIdx.x * BM;
    const int w    = tid >> 5, lane = tid & 31;
    const int wm   = w >> 1, wn = w & 1;
    const int m0w  = wm * 32, n0w = wn * 64;
    const int r    = lane >> 2, cg = lane & 3;

    // ldmatrix per-lane address components
    const int a_row = (lane & 7) | (lane & 8);          // +8 for lanes 8-15,24-31
    const int a_c4  = (lane & 16) >> 2;                 // k-hi half for lanes 16-31
    const int b_row = (lane & 7) | ((lane & 16) >> 1);  // +8 for lanes 16-31
    const int b_c4  = (lane & 8) >> 1;                  // k-hi half for lanes 8-15,24-31

    float acc[2][8][4];
#pragma unroll
    for (int i = 0; i < 2; i++)
#pragma unroll
        for (int j = 0; j < 8; j++)
#pragma unroll
            for (int t = 0; t < 4; t++) acc[i][j][t] = 0.f;

    const int srow = tid >> 3;
    const int skc  = (tid & 7) * 4;

    uint2 sa2[4], sb2[4];
    auto loadA = [&](int i, int kbase) {
        int row = srow + i * 32;
        int gm = bm + row;
        if (EPI == 0) {
            float4 a = (gm < M_TOT)
                ? *(const float4*)(Af + (size_t)gm * K + kbase + skc)
                : make_float4(0, 0, 0, 0);
            sa2[i] = make_uint2(pack2(a.x, a.y), pack2(a.z, a.w));
        } else {
            sa2[i] = (gm < M_TOT)
                ? *(const uint2*)(Ah + (size_t)gm * K + kbase + skc)
                : make_uint2(0, 0);
        }
    };
    auto loadB = [&](int i, int kbase) {
        int row = srow + i * 32;
        float4 b = *(const float4*)(W + (size_t)(bn + row) * K + kbase + skc);
        sb2[i] = make_uint2(pack2(b.x, b.y), pack2(b.z, b.w));
    };

#pragma unroll
    for (int i = 0; i < 4; i++) { loadA(i, 0); loadB(i, 0); }
#pragma unroll
    for (int i = 0; i < 4; i++) {
        int row = srow + i * 32;
        *(uint2*)&Asb[row * TSTR + (skc >> 1)] = sa2[i];
        *(uint2*)&Bsb[row * TSTR + (skc >> 1)] = sb2[i];
    }
    __syncthreads();

    int buf = 0;
    for (int kc0 = 0; kc0 < K; kc0 += 32) {
        const bool more = (kc0 + 32) < K;
        if (more) {
#pragma unroll
            for (int i = 0; i < 4; i++) { loadA(i, kc0 + 32); loadB(i, kc0 + 32); }
        }

        const unsigned abuf = as_base + buf * BUFSZ * 4;
        const unsigned bbuf = bs_base + buf * BUFSZ * 4;
#pragma unroll
        for (int ks = 0; ks < 2; ks++) {
            const int kb = ks * 8;
            unsigned af[2][4], bf[8][2];
#pragma unroll
            for (int mt = 0; mt < 2; mt++) {
                unsigned aaddr = abuf +
                    ((m0w + mt * 16 + a_row) * TSTR + kb + a_c4) * 4;
                ldsm_x4(af[mt][0], af[mt][1], af[mt][2], af[mt][3], aaddr);
            }
#pragma unroll
            for (int j = 0; j < 8; j += 2) {
                unsigned baddr = bbuf +
                    ((n0w + j * 8 + b_row) * TSTR + kb + b_c4) * 4;
                ldsm_x4(bf[j][0], bf[j][1], bf[j + 1][0], bf[j + 1][1], baddr);
            }
#pragma unroll
            for (int mt = 0; mt < 2; mt++)
#pragma unroll
                for (int nt = 0; nt < 8; nt++)
                    mma_f16(acc[mt][nt][0], acc[mt][nt][1],
                            acc[mt][nt][2], acc[mt][nt][3],
                            af[mt][0], af[mt][1], af[mt][2], af[mt][3],
                            bf[nt][0], bf[nt][1]);
        }

        if (more) {
            unsigned* An = Asb + (buf ^ 1) * BUFSZ;
            unsigned* Bn = Bsb + (buf ^ 1) * BUFSZ;
#pragma unroll
            for (int i = 0; i < 4; i++) {
                int row = srow + i * 32;
                *(uint2*)&An[row * TSTR + (skc >> 1)] = sa2[i];
                *(uint2*)&Bn[row * TSTR + (skc >> 1)] = sb2[i];
            }
            __syncthreads();
            buf ^= 1;
        }
    }

    // Epilogue
#pragma unroll
    for (int mt = 0; mt < 2; mt++) {
        int mbase = bm + m0w + mt * 16;
#pragma unroll
        for (int nt = 0; nt < 8; nt++) {
            int nbase = bn + n0w + nt * 8 + 2 * cg;
#pragma unroll
            for (int half = 0; half < 2; half++) {
                int row = mbase + r + half * 8;
                if (row >= M_TOT) continue;
                float v0 = acc[mt][nt][half * 2 + 0];
                float v1 = acc[mt][nt][half * 2 + 1];
                if (EPI == 1) {
                    *(float2*)&out[(size_t)row * Cc + nbase] =
                        make_float2(v0 + b0v[nbase], v1 + b0v[nbase + 1]);
                } else {
                    int bI = row / Nn, n = row % Nn;
                    int which = nbase / Cc;
                    int cc = nbase % Cc;
                    int h = cc >> 6, d = cc & 63;
                    size_t off = (((size_t)bI * Hh + h) * Nn + n) * Dd + d;
                    if (which == 0)
                        *(unsigned*)&g_q[off] = pack2((v0 + b0v[cc]) * 0.125f,
                                                      (v1 + b0v[cc + 1]) * 0.125f);
                    else if (which == 1)
                        *(unsigned*)&g_k[off] = pack2(v0 + b1v[cc], v1 + b1v[cc + 1]);
                    else
                        *(unsigned*)&g_v[off] = pack2(v0 + b2v[cc], v1 + b2v[cc + 1]);
                }
            }
        }
    }
}

// ---------------------------------------------------------------------------
// Kernel 3: fused attention, fp16 mma + ldmatrix. 256 threads, 8 warps (2x4).
// smem (u32): Qs[64][36] | KVs[64][36] | Ss[64][260] f32 (probs packed in place)
// total 84992 B
// ---------------------------------------------------------------------------
__global__ __launch_bounds__(256) void attn_fused() {
    extern __shared__ unsigned smemu[];
    unsigned* Qs  = smemu;                    // stride 36
    unsigned* KVs = smemu + 64 * 36;
    float*    Ss  = (float*)(smemu + 2 * 64 * 36);

    const unsigned qs_base = (unsigned)__cvta_generic_to_shared(Qs);
    const unsigned kv_base = (unsigned)__cvta_generic_to_shared(KVs);
    const unsigned ss_base = (unsigned)__cvta_generic_to_shared(Ss);

    const int bh = blockIdx.y, h = bh % Hh, bI = bh / Hh;
    const int m0 = blockIdx.x * 64;
    const int tid = threadIdx.x, lane = tid & 31, w = tid >> 5;
    const int wm = w >> 2;          // 0..1
    const int wn = w & 3;           // 0..3
    const int r = lane >> 2, cg = lane & 3;
    const __half* qb = g_q + (size_t)bh * Nn * Dd;
    const __half* kb = g_k + (size_t)bh * Nn * Dd;
    const __half* vb = g_v + (size_t)bh * Nn * Dd;

    const int a_row = (lane & 7) | (lane & 8);
    const int a_c4  = (lane & 16) >> 2;
    const int b_row = (lane & 7) | ((lane & 16) >> 1);
    const int b_c4  = (lane & 8) >> 1;

    // ---- load Q tile ----
#pragma unroll
    for (int i = 0; i < 2; i++) {
        int s = tid + i * 256;
        int row = s >> 3, c4 = (s & 7);
        uint4 v = (m0 + row < Nn)
            ? ((const uint4*)(qb + (size_t)(m0 + row) * Dd))[c4]
            : make_uint4(0, 0, 0, 0);
        *(uint4*)&Qs[row * 36 + c4 * 4] = v;
    }

    // ---- scores: 4 K-tiles of 64 tokens ----
    for (int nt0 = 0; nt0 < 4; nt0++) {
        const int n0 = nt0 * 64;
        __syncthreads();
#pragma unroll
        for (int i = 0; i < 2; i++) {
            int s = tid + i * 256;
            int row = s >> 3, c4 = (s & 7);
            uint4 v = (n0 + row < Nn)
                ? ((const uint4*)(kb + (size_t)(n0 + row) * Dd))[c4]
                : make_uint4(0, 0, 0, 0);
            *(uint4*)&KVs[row * 36 + c4 * 4] = v;
        }
        __syncthreads();

        float acc[2][2][4];
#pragma unroll
        for (int i = 0; i < 2; i++)
#pragma unroll
            for (int j = 0; j < 2; j++)
#pragma unroll
                for (int t = 0; t < 4; t++) acc[i][j][t] = 0.f;

#pragma unroll
        for (int ks = 0; ks < 4; ks++) {
            const int kbu = ks * 8;
            unsigned af[2][4], bf[2][2];
#pragma unroll
            for (int mt = 0; mt < 2; mt++) {
                unsigned aaddr = qs_base +
                    ((wm * 32 + mt * 16 + a_row) * 36 + kbu + a_c4) * 4;
                ldsm_x4(af[mt][0], af[mt][1], af[mt][2], af[mt][3], aaddr);
            }
            {
                unsigned baddr = kv_base +
                    ((wn * 16 + b_row) * 36 + kbu + b_c4) * 4;
                ldsm_x4(bf[0][0], bf[0][1], bf[1][0], bf[1][1], baddr);
            }
#pragma unroll
            for (int mt = 0; mt < 2; mt++)
#pragma unroll
                for (int nt = 0; nt < 2; nt++)
                    mma_f16(acc[mt][nt][0], acc[mt][nt][1],
                            acc[mt][nt][2], acc[mt][nt][3],
                            af[mt][0], af[mt][1], af[mt][2], af[mt][3],
                            bf[nt][0], bf[nt][1]);
        }

        // write S tile (+rpb) fp32; out-of-range -> 0
#pragma unroll
        for (int mt = 0; mt < 2; mt++) {
            int mlb = wm * 32 + mt * 16;
#pragma unroll
            for (int nt = 0; nt < 2; nt++) {
                int nl = wn * 16 + nt * 8 + 2 * cg;
#pragma unroll
                for (int half = 0; half < 2; half++) {
                    int ml = mlb + r + half * 8;
                    int mg = m0 + ml;
                    float v0 = 0.f, v1 = 0.f;
                    if (mg < Nn) {
                        int ng0 = n0 + nl, ng1 = ng0 + 1;
                        const float* rp = g_rpb + ((size_t)h * Nn + mg) * Nn;
                        if (ng0 < Nn) v0 = acc[mt][nt][half * 2 + 0] + rp[ng0];
                        if (ng1 < Nn) v1 = acc[mt][nt][half * 2 + 1] + rp[ng1];
                    }
                    *(float2*)&Ss[ml * SLD + n0 + nl] = make_float2(v0, v1);
                }
            }
        }
    }
    __syncthreads();

    // ---- softmax per row + pack to half2 in place ----
    for (int row = w; row < 64; row += 8) {
        float* sr = Ss + row * SLD;
        float mx = -1e30f;
        for (int j = lane; j < Nn; j += 32) mx = fmaxf(mx, sr[j]);
#pragma unroll
        for (int o = 16; o; o >>= 1) mx = fmaxf(mx, __shfl_xor_sync(0xffffffffu, mx, o));
        float s = 0.f;
        for (int j = lane; j < Nn; j += 32) {
            float e = __expf(sr[j] - mx);
            sr[j] = e;
            s += e;
        }
#pragma unroll
        for (int o = 16; o; o >>= 1) s += __shfl_xor_sync(0xffffffffu, s, o);
        float inv = 1.f / s;
        unsigned* pu = (unsigned*)sr;
#pragma unroll
        for (int j4 = 0; j4 < 4; j4++) {
            int j = lane + j4 * 32;
            float2 p = *(float2*)&sr[2 * j];
            __syncwarp();
            pu[j] = pack2(p.x * inv, p.y * inv);
        }
    }

    // ---- PV: O = P @ V over 4 chunks of 64 tokens ----
    float accO[2][2][4];
#pragma unroll
    for (int i = 0; i < 2; i++)
#pragma unroll
        for (int j = 0; j < 2; j++)
#pragma unroll
            for (int t = 0; t < 4; t++) accO[i][j][t] = 0.f;

    for (int c = 0; c < 4; c++) {
        const int k0 = c * 64;
        __syncthreads();
        // stage V transposed: KVs[d][tokpair]
#pragma unroll
        for (int i = 0; i < 2; i++) {
            int s = tid + i * 256;
            int tp = s & 31, dc = (s >> 5) * 4;
            int t0 = k0 + 2 * tp;
            uint2 h0 = (t0 < Nn)     ? *(const uint2*)(vb + (size_t)t0 * Dd + dc)
                                     : make_uint2(0, 0);
            uint2 h1 = (t0 + 1 < Nn) ? *(const uint2*)(vb + (size_t)(t0 + 1) * Dd + dc)
                                     : make_uint2(0, 0);
            const __half* a = (const __half*)&h0;
            const __half* b = (const __half*)&h1;
#pragma unroll
            for (int e = 0; e < 4; e++) {
                __half2 hv = __halves2half2(a[e], b[e]);
                KVs[(dc + e) * 36 + tp] = *reinterpret_cast<unsigned*>(&hv);
            }
        }
        __syncthreads();

#pragma unroll
        for (int ks = 0; ks < 4; ks++) {
            const int kbu = c * 32 + ks * 8;
            unsigned af[2][4], bf[2][2];
#pragma unroll
            for (int mt = 0; mt < 2; mt++) {
                unsigned aaddr = ss_base +
                    ((wm * 32 + mt * 16 + a_row) * SLD + kbu + a_c4) * 4;
                ldsm_x4(af[mt][0], af[mt][1], af[mt][2], af[mt][3], aaddr);
            }
            {
                unsigned baddr = kv_base +
                    ((wn * 16 + b_row) * 36 + ks * 8 + b_c4) * 4;
                ldsm_x4(bf[0][0], bf[0][1], bf[1][0], bf[1][1], baddr);
            }
#pragma unroll
            for (int mt = 0; mt < 2; mt++)
#pragma unroll
                for (int nt = 0; nt < 2; nt++)
                    mma_f16(accO[mt][nt][0], accO[mt][nt][1],
                            accO[mt][nt][2], accO[mt][nt][3],
                            af[mt][0], af[mt][1], af[mt][2], af[mt][3],
                            bf[nt][0], bf[nt][1]);
        }
    }

    // ---- store O tile (fp16) ----
#pragma unroll
    for (int mt = 0; mt < 2; mt++) {
        int mbase = m0 + wm * 32 + mt * 16;
#pragma unroll
        for (int nt = 0; nt < 2; nt++) {
            int nb = wn * 16 + nt * 8 + 2 * cg;
#pragma unroll
            for (int half = 0; half < 2; half++) {
                int m = mbase + r + half * 8;
                if (m >= Nn) continue;
                size_t o = ((size_t)bI * Nn + m) * Cc + h * Dd + nb;
                *(unsigned*)&g_o[o] = pack2(accO[mt][nt][half * 2 + 0],
                                            accO[mt][nt][half * 2 + 1]);
            }
        }
    }
}

// ---------------------------------------------------------------------------
extern "C" void kernel_launch(void* const* d_in, const int* in_sizes, int n_in,
                              void* d_out, int out_size)
{
    const float* x         = (const float*)d_in[0];
    const float* qkv_w     = (const float*)d_in[1];
    const float* q_bias    = (const float*)d_in[2];
    const float* k_bias    = (const float*)d_in[3];
    const float* v_bias    = (const float*)d_in[4];
    const float* rel_table = (const float*)d_in[5];
    const float* proj_w    = (const float*)d_in[6];
    const float* proj_b    = (const float*)d_in[7];
    float* out = (float*)d_out;

    constexpr int GEMM_SMEM = 4 * 128 * 20 * 4;                   // 40960
    constexpr int ATTN_SMEM = (2 * 64 * 36 + 64 * SLD) * 4;       // 84992

    static bool attr_done = false;
    if (!attr_done) {
        cudaFuncSetAttribute(gemm_f16<0>, cudaFuncAttributeMaxDynamicSharedMemorySize, GEMM_SMEM);
        cudaFuncSetAttribute(gemm_f16<1>, cudaFuncAttributeMaxDynamicSharedMemorySize, GEMM_SMEM);
        cudaFuncSetAttribute(attn_fused,  cudaFuncAttributeMaxDynamicSharedMemorySize, ATTN_SMEM);
        attr_done = true;
    }

    {
        int total = Hh * Nn * Nn;
        rpb_kernel<<<(total + 255) / 256, 256>>>(rel_table);
    }
    {
        dim3 grid(3 * Cc / 128, (M_TOT + 127) / 128);
        gemm_f16<0><<<grid, 256, GEMM_SMEM>>>(x, qkv_w, q_bias, k_bias, v_bias, nullptr);
    }
    {
        dim3 grid((Nn + 63) / 64, Bb * Hh);
        attn_fused<<<grid, 256, ATTN_SMEM>>>();
    }
    {
        dim3 grid(Cc / 128, (M_TOT + 127) / 128);
        gemm_f16<1><<<grid, 256, GEMM_SMEM>>>(nullptr, proj_w, proj_b, nullptr, nullptr, out);
    }
}

// round 9
// speedup vs baseline: 4.6968x; 1.1233x over previous
#include <cuda_runtime.h>
#include <cuda_fp16.h>
#include <cstddef>
#include <cstdint>

// Problem constants
constexpr int Bb  = 64;
constexpr int Nn  = 197;
constexpr int Cc  = 768;
constexpr int Hh  = 12;
constexpr int Dd  = 64;
constexpr int M_TOT = Bb * Nn;        // 12608
constexpr int SLD  = 212;             // S row stride (floats): 208 cols + 4 pad

// Scratch (device globals) — fp16
__device__ __half g_q[(size_t)Bb * Hh * Nn * Dd];
__device__ __half g_k[(size_t)Bb * Hh * Nn * Dd];
__device__ __half g_v[(size_t)Bb * Hh * Nn * Dd];
__device__ float  g_rpb[(size_t)Hh * Nn * Nn];
__device__ __half g_o[(size_t)Bb * Nn * Cc];

// ---------------------------------------------------------------------------
// helpers
// ---------------------------------------------------------------------------
__device__ __forceinline__ unsigned pack2(float x, float y) {
    __half2 h = __float22half2_rn(make_float2(x, y));
    return *reinterpret_cast<unsigned*>(&h);
}

__device__ __forceinline__ void mma_f16(
    float& c0, float& c1, float& c2, float& c3,
    unsigned a0, unsigned a1, unsigned a2, unsigned a3,
    unsigned b0, unsigned b1)
{
    asm volatile(
        "mma.sync.aligned.m16n8k16.row.col.f32.f16.f16.f32 "
        "{%0,%1,%2,%3},{%4,%5,%6,%7},{%8,%9},{%0,%1,%2,%3};\n"
        : "+f"(c0), "+f"(c1), "+f"(c2), "+f"(c3)
        : "r"(a0), "r"(a1), "r"(a2), "r"(a3), "r"(b0), "r"(b1));
}

__device__ __forceinline__ void ldsm_x4(
    unsigned& r0, unsigned& r1, unsigned& r2, unsigned& r3, unsigned addr)
{
    asm volatile("ldmatrix.sync.aligned.m8n8.x4.shared.b16 {%0,%1,%2,%3}, [%4];"
                 : "=r"(r0), "=r"(r1), "=r"(r2), "=r"(r3) : "r"(addr));
}

__device__ __forceinline__ void ldsm_x4_trans(
    unsigned& r0, unsigned& r1, unsigned& r2, unsigned& r3, unsigned addr)
{
    asm volatile("ldmatrix.sync.aligned.m8n8.x4.trans.shared.b16 {%0,%1,%2,%3}, [%4];"
                 : "=r"(r0), "=r"(r1), "=r"(r2), "=r"(r3) : "r"(addr));
}

__device__ __forceinline__ void cp16(unsigned dst, const void* src) {
    asm volatile("cp.async.ca.shared.global [%0], [%1], 16;"
                 :: "r"(dst), "l"(src) : "memory");
}
__device__ __forceinline__ void cp_commit() {
    asm volatile("cp.async.commit_group;" ::: "memory");
}
__device__ __forceinline__ void cp_wait0() {
    asm volatile("cp.async.wait_group 0;" ::: "memory");
}

// ---------------------------------------------------------------------------
// Kernel 1: relative position bias gather
// ---------------------------------------------------------------------------
__global__ void rpb_kernel(const float* __restrict__ rel_table) {
    int tid = blockIdx.x * blockDim.x + threadIdx.x;
    const int total = Hh * Nn * Nn;
    if (tid >= total) return;
    int h = tid / (Nn * Nn);
    int r = tid % (Nn * Nn);
    int i = r / Nn, j = r % Nn;
    int idx;
    if (i == 0 && j == 0)      idx = 731;
    else if (i == 0)           idx = 729;
    else if (j == 0)           idx = 730;
    else {
        int a = i - 1, b = j - 1;
        int d0 = (a / 14 - b / 14) + 13;
        int d1 = (a % 14 - b % 14) + 13;
        idx = d0 * 27 + d1;
    }
    g_rpb[tid] = rel_table[idx * Hh + h];
}

// ---------------------------------------------------------------------------
// Kernels 2 & 4: fp16 GEMM  C = A @ W^T (+bias), ping-pong smem + ldmatrix
// (proven R6 version, unchanged)
// ---------------------------------------------------------------------------
template <int EPI>
__global__ __launch_bounds__(256) void gemm_f16(
    const float* __restrict__ Af, const float* __restrict__ W,
    const float* __restrict__ b0v, const float* __restrict__ b1v,
    const float* __restrict__ b2v, float* __restrict__ out)
{
    constexpr int K = 768, BM = 128;
    constexpr int TSTR = 20;
    constexpr int BUFSZ = BM * TSTR;
    extern __shared__ unsigned gsm[];
    unsigned* Asb = gsm;
    unsigned* Bsb = gsm + 2 * BUFSZ;

    const unsigned as_base = (unsigned)__cvta_generic_to_shared(Asb);
    const unsigned bs_base = (unsigned)__cvta_generic_to_shared(Bsb);

    const __half* Ah = (const __half*)g_o;
    const int tid  = threadIdx.x;
    const int bm   = blockIdx.y * BM;
    const int bn   = blockIdx.x * BM;
    const int w    = tid >> 5, lane = tid & 31;
    const int wm   = w >> 1, wn = w & 1;
    const int m0w  = wm * 32, n0w = wn * 64;
    const int r    = lane >> 2, cg = lane & 3;

    const int a_row = (lane & 7) | (lane & 8);
    const int a_c4  = (lane & 16) >> 2;
    const int b_row = (lane & 7) | ((lane & 16) >> 1);
    const int b_c4  = (lane & 8) >> 1;

    float acc[2][8][4];
#pragma unroll
    for (int i = 0; i < 2; i++)
#pragma unroll
        for (int j = 0; j < 8; j++)
#pragma unroll
            for (int t = 0; t < 4; t++) acc[i][j][t] = 0.f;

    const int srow = tid >> 3;
    const int skc  = (tid & 7) * 4;

    uint2 sa2[4], sb2[4];
    auto loadA = [&](int i, int kbase) {
        int row = srow + i * 32;
        int gm = bm + row;
        if (EPI == 0) {
            float4 a = (gm < M_TOT)
                ? *(const float4*)(Af + (size_t)gm * K + kbase + skc)
                : make_float4(0, 0, 0, 0);
            sa2[i] = make_uint2(pack2(a.x, a.y), pack2(a.z, a.w));
        } else {
            sa2[i] = (gm < M_TOT)
                ? *(const uint2*)(Ah + (size_t)gm * K + kbase + skc)
                : make_uint2(0, 0);
        }
    };
    auto loadB = [&](int i, int kbase) {
        int row = srow + i * 32;
        float4 b = *(const float4*)(W + (size_t)(bn + row) * K + kbase + skc);
        sb2[i] = make_uint2(pack2(b.x, b.y), pack2(b.z, b.w));
    };

#pragma unroll
    for (int i = 0; i < 4; i++) { loadA(i, 0); loadB(i, 0); }
#pragma unroll
    for (int i = 0; i < 4; i++) {
        int row = srow + i * 32;
        *(uint2*)&Asb[row * TSTR + (skc >> 1)] = sa2[i];
        *(uint2*)&Bsb[row * TSTR + (skc >> 1)] = sb2[i];
    }
    __syncthreads();

    int buf = 0;
    for (int kc0 = 0; kc0 < K; kc0 += 32) {
        const bool more = (kc0 + 32) < K;
        if (more) {
#pragma unroll
            for (int i = 0; i < 4; i++) { loadA(i, kc0 + 32); loadB(i, kc0 + 32); }
        }

        const unsigned abuf = as_base + buf * BUFSZ * 4;
        const unsigned bbuf = bs_base + buf * BUFSZ * 4;
#pragma unroll
        for (int ks = 0; ks < 2; ks++) {
            const int kb = ks * 8;
            unsigned af[2][4], bf[8][2];
#pragma unroll
            for (int mt = 0; mt < 2; mt++) {
                unsigned aaddr = abuf +
                    ((m0w + mt * 16 + a_row) * TSTR + kb + a_c4) * 4;
                ldsm_x4(af[mt][0], af[mt][1], af[mt][2], af[mt][3], aaddr);
            }
#pragma unroll
            for (int j = 0; j < 8; j += 2) {
                unsigned baddr = bbuf +
                    ((n0w + j * 8 + b_row) * TSTR + kb + b_c4) * 4;
                ldsm_x4(bf[j][0], bf[j][1], bf[j + 1][0], bf[j + 1][1], baddr);
            }
#pragma unroll
            for (int mt = 0; mt < 2; mt++)
#pragma unroll
                for (int nt = 0; nt < 8; nt++)
                    mma_f16(acc[mt][nt][0], acc[mt][nt][1],
                            acc[mt][nt][2], acc[mt][nt][3],
                            af[mt][0], af[mt][1], af[mt][2], af[mt][3],
                            bf[nt][0], bf[nt][1]);
        }

        if (more) {
            unsigned* An = Asb + (buf ^ 1) * BUFSZ;
            unsigned* Bn = Bsb + (buf ^ 1) * BUFSZ;
#pragma unroll
            for (int i = 0; i < 4; i++) {
                int row = srow + i * 32;
                *(uint2*)&An[row * TSTR + (skc >> 1)] = sa2[i];
                *(uint2*)&Bn[row * TSTR + (skc >> 1)] = sb2[i];
            }
            __syncthreads();
            buf ^= 1;
        }
    }

#pragma unroll
    for (int mt = 0; mt < 2; mt++) {
        int mbase = bm + m0w + mt * 16;
#pragma unroll
        for (int nt = 0; nt < 8; nt++) {
            int nbase = bn + n0w + nt * 8 + 2 * cg;
#pragma unroll
            for (int half = 0; half < 2; half++) {
                int row = mbase + r + half * 8;
                if (row >= M_TOT) continue;
                float v0 = acc[mt][nt][half * 2 + 0];
                float v1 = acc[mt][nt][half * 2 + 1];
                if (EPI == 1) {
                    *(float2*)&out[(size_t)row * Cc + nbase] =
                        make_float2(v0 + b0v[nbase], v1 + b0v[nbase + 1]);
                } else {
                    int bI = row / Nn, n = row % Nn;
                    int which = nbase / Cc;
                    int cc = nbase % Cc;
                    int h = cc >> 6, d = cc & 63;
                    size_t off = (((size_t)bI * Hh + h) * Nn + n) * Dd + d;
                    if (which == 0)
                        *(unsigned*)&g_q[off] = pack2((v0 + b0v[cc]) * 0.125f,
                                                      (v1 + b0v[cc + 1]) * 0.125f);
                    else if (which == 1)
                        *(unsigned*)&g_k[off] = pack2(v0 + b1v[cc], v1 + b1v[cc + 1]);
                    else
                        *(unsigned*)&g_v[off] = pack2(v0 + b2v[cc], v1 + b2v[cc + 1]);
                }
            }
        }
    }
}

// ---------------------------------------------------------------------------
// Kernel 3: fused attention v2 (R8) + V pad zero-fill fix.
// 256 threads, 8 warps (2m x 4n). K fully resident, 3 syncthreads total.
// smem (u32): Qs[64][36] | Ks[256][36] (V overlays) | Ss[64][212] f32
// total 100352 B -> 2 CTA/SM
// ---------------------------------------------------------------------------
__global__ __launch_bounds__(256) void attn_fused() {
    extern __shared__ unsigned smemu[];
    unsigned* Qs = smemu;                       // [64][36]
    unsigned* Ks = smemu + 64 * 36;             // [256][36]; V overlays after scores
    float*    Ss = (float*)(smemu + 64 * 36 + 256 * 36);  // [64][212]

    const unsigned qs_base = (unsigned)__cvta_generic_to_shared(Qs);
    const unsigned ks_base = (unsigned)__cvta_generic_to_shared(Ks);
    const unsigned ss_base = (unsigned)__cvta_generic_to_shared(Ss);

    const int bh = blockIdx.y, h = bh % Hh, bI = bh / Hh;
    const int m0 = blockIdx.x * 64;
    const int tid = threadIdx.x, lane = tid & 31, w = tid >> 5;
    const int wm = w >> 2;          // 0..1 : 32 m-rows
    const int wn = w & 3;           // 0..3 : 16 n-cols
    const int r = lane >> 2, cg = lane & 3;
    const __half* qb = g_q + (size_t)bh * Nn * Dd;
    const __half* kb = g_k + (size_t)bh * Nn * Dd;
    const __half* vb = g_v + (size_t)bh * Nn * Dd;

    const int a_row = (lane & 7) | (lane & 8);
    const int a_c4  = (lane & 16) >> 2;
    const int b_row = (lane & 7) | ((lane & 16) >> 1);
    const int b_c4  = (lane & 8) >> 1;

    // ---- stage Q (64 rows) + K (197 rows) via cp.async ----
    for (int s = tid; s < 64 * 8; s += 256) {
        int row = s >> 3, c4 = s & 7;
        if (m0 + row < Nn)
            cp16(qs_base + (row * 36 + c4 * 4) * 4,
                 qb + (size_t)(m0 + row) * Dd + c4 * 8);
    }
    for (int s = tid; s < 197 * 8; s += 256) {
        int row = s >> 3, c4 = s & 7;
        cp16(ks_base + (row * 36 + c4 * 4) * 4,
             kb + (size_t)row * Dd + c4 * 8);
    }
    cp_commit();
    cp_wait0();
    __syncthreads();

    // ---- scores: 4 n-tiles, no barriers in between ----
    for (int nt0 = 0; nt0 < 4; nt0++) {
        const int n0 = nt0 * 64;
        float acc[2][2][4];
#pragma unroll
        for (int i = 0; i < 2; i++)
#pragma unroll
            for (int j = 0; j < 2; j++)
#pragma unroll
                for (int t = 0; t < 4; t++) acc[i][j][t] = 0.f;

#pragma unroll
        for (int ks = 0; ks < 4; ks++) {
            const int kbu = ks * 8;
            unsigned af[2][4], bf[2][2];
#pragma unroll
            for (int mt = 0; mt < 2; mt++) {
                unsigned aaddr = qs_base +
                    ((wm * 32 + mt * 16 + a_row) * 36 + kbu + a_c4) * 4;
                ldsm_x4(af[mt][0], af[mt][1], af[mt][2], af[mt][3], aaddr);
            }
            {
                unsigned baddr = ks_base +
                    ((n0 + wn * 16 + b_row) * 36 + kbu + b_c4) * 4;
                ldsm_x4(bf[0][0], bf[0][1], bf[1][0], bf[1][1], baddr);
            }
#pragma unroll
            for (int mt = 0; mt < 2; mt++)
#pragma unroll
                for (int nt = 0; nt < 2; nt++)
                    mma_f16(acc[mt][nt][0], acc[mt][nt][1],
                            acc[mt][nt][2], acc[mt][nt][3],
                            af[mt][0], af[mt][1], af[mt][2], af[mt][3],
                            bf[nt][0], bf[nt][1]);
        }

        // write S tile (+rpb); cols >= 208 skipped; invalid cells -> 0
#pragma unroll
        for (int mt = 0; mt < 2; mt++) {
            int mlb = wm * 32 + mt * 16;
#pragma unroll
            for (int nt = 0; nt < 2; nt++) {
                int nl = wn * 16 + nt * 8 + 2 * cg;
                if (n0 + nl >= 208) continue;
#pragma unroll
                for (int half = 0; half < 2; half++) {
                    int ml = mlb + r + half * 8;
                    int mg = m0 + ml;
                    float v0 = 0.f, v1 = 0.f;
                    if (mg < Nn) {
                        int ng0 = n0 + nl, ng1 = ng0 + 1;
                        const float* rp = g_rpb + ((size_t)h * Nn + mg) * Nn;
                        if (ng0 < Nn) v0 = acc[mt][nt][half * 2 + 0] + rp[ng0];
                        if (ng1 < Nn) v1 = acc[mt][nt][half * 2 + 1] + rp[ng1];
                    }
                    *(float2*)&Ss[ml * SLD + n0 + nl] = make_float2(v0, v1);
                }
            }
        }
    }
    __syncthreads();   // scores done (Ks reads finished), S fully written

    // ---- stage V into Ks region (overlaps with softmax) ----
    // Rows 197..207 are READ by the PV ldsm.trans (13 k-steps cover tokens
    // 0..207) — they MUST be zeroed, else garbage fp16 (possibly Inf/NaN)
    // multiplies zero-probability pads and poisons the accumulator.
    for (int s = tid; s < 208 * 8; s += 256) {
        int row = s >> 3, c4 = s & 7;
        if (row < Nn)
            cp16(ks_base + (row * 36 + c4 * 4) * 4,
                 vb + (size_t)row * Dd + c4 * 8);
        else
            *(uint4*)&Ks[row * 36 + c4 * 4] = make_uint4(0, 0, 0, 0);
    }
    cp_commit();

    // ---- softmax per row (one warp per row, 8 rows/warp), pack to half2 ----
    for (int row = w; row < 64; row += 8) {
        float* sr = Ss + row * SLD;
        float mx = -1e30f;
        for (int j = lane; j < Nn; j += 32) mx = fmaxf(mx, sr[j]);
#pragma unroll
        for (int o = 16; o; o >>= 1) mx = fmaxf(mx, __shfl_xor_sync(0xffffffffu, mx, o));
        float s = 0.f;
        for (int j = lane; j < Nn; j += 32) {
            float e = __expf(sr[j] - mx);
            sr[j] = e;
            s += e;
        }
#pragma unroll
        for (int o = 16; o; o >>= 1) s += __shfl_xor_sync(0xffffffffu, s, o);
        float inv = 1.f / s;
        unsigned* pu = (unsigned*)sr;
#pragma unroll
        for (int j4 = 0; j4 < 4; j4++) {
            int j = lane + j4 * 32;               // pair index; need j < 104
            float2 p;
            if (j < 104) p = *(float2*)&sr[2 * j];
            __syncwarp();
            if (j < 104) pu[j] = pack2(p.x * inv, p.y * inv);
        }
    }

    cp_wait0();
    __syncthreads();   // V visible to all; probs packed

    // ---- PV: 13 k16-steps over tokens 0..207; V consumed via ldsm.trans ----
    float accO[2][2][4];
#pragma unroll
    for (int i = 0; i < 2; i++)
#pragma unroll
        for (int j = 0; j < 2; j++)
#pragma unroll
            for (int t = 0; t < 4; t++) accO[i][j][t] = 0.f;

#pragma unroll
    for (int kst = 0; kst < 13; kst++) {
        const int kbu = kst * 8;                  // u32 offset in packed P row
        unsigned af[2][4], bf[2][2];
#pragma unroll
        for (int mt = 0; mt < 2; mt++) {
            unsigned aaddr = ss_base +
                ((wm * 32 + mt * 16 + a_row) * SLD + kbu + a_c4) * 4;
            ldsm_x4(af[mt][0], af[mt][1], af[mt][2], af[mt][3], aaddr);
        }
        {
            // trans ldsm: rows = tokens, cols = head dims -> B-frag (k=tok, n=d)
            unsigned vaddr = ks_base +
                (((kst * 16 + (lane & 15)) * 36) + wn * 8 + ((lane >> 4) * 4)) * 4;
            ldsm_x4_trans(bf[0][0], bf[0][1], bf[1][0], bf[1][1], vaddr);
        }
#pragma unroll
        for (int mt = 0; mt < 2; mt++)
#pragma unroll
            for (int nt = 0; nt < 2; nt++)
                mma_f16(accO[mt][nt][0], accO[mt][nt][1],
                        accO[mt][nt][2], accO[mt][nt][3],
                        af[mt][0], af[mt][1], af[mt][2], af[mt][3],
                        bf[nt][0], bf[nt][1]);
    }

    // ---- store O tile (fp16) ----
#pragma unroll
    for (int mt = 0; mt < 2; mt++) {
        int mbase = m0 + wm * 32 + mt * 16;
#pragma unroll
        for (int nt = 0; nt < 2; nt++) {
            int nb = wn * 16 + nt * 8 + 2 * cg;
#pragma unroll
            for (int half = 0; half < 2; half++) {
                int m = mbase + r + half * 8;
                if (m >= Nn) continue;
                size_t o = ((size_t)bI * Nn + m) * Cc + h * Dd + nb;
                *(unsigned*)&g_o[o] = pack2(accO[mt][nt][half * 2 + 0],
                                            accO[mt][nt][half * 2 + 1]);
            }
        }
    }
}

// ---------------------------------------------------------------------------
extern "C" void kernel_launch(void* const* d_in, const int* in_sizes, int n_in,
                              void* d_out, int out_size)
{
    const float* x         = (const float*)d_in[0];
    const float* qkv_w     = (const float*)d_in[1];
    const float* q_bias    = (const float*)d_in[2];
    const float* k_bias    = (const float*)d_in[3];
    const float* v_bias    = (const float*)d_in[4];
    const float* rel_table = (const float*)d_in[5];
    const float* proj_w    = (const float*)d_in[6];
    const float* proj_b    = (const float*)d_in[7];
    float* out = (float*)d_out;

    constexpr int GEMM_SMEM = 4 * 128 * 20 * 4;                       // 40960
    constexpr int ATTN_SMEM = (64 * 36 + 256 * 36 + 64 * SLD) * 4;    // 100352

    static bool attr_done = false;
    if (!attr_done) {
        cudaFuncSetAttribute(gemm_f16<0>, cudaFuncAttributeMaxDynamicSharedMemorySize, GEMM_SMEM);
        cudaFuncSetAttribute(gemm_f16<1>, cudaFuncAttributeMaxDynamicSharedMemorySize, GEMM_SMEM);
        cudaFuncSetAttribute(attn_fused,  cudaFuncAttributeMaxDynamicSharedMemorySize, ATTN_SMEM);
        attr_done = true;
    }

    {
        int total = Hh * Nn * Nn;
        rpb_kernel<<<(total + 255) / 256, 256>>>(rel_table);
    }
    {
        dim3 grid(3 * Cc / 128, (M_TOT + 127) / 128);
        gemm_f16<0><<<grid, 256, GEMM_SMEM>>>(x, qkv_w, q_bias, k_bias, v_bias, nullptr);
    }
    {
        dim3 grid((Nn + 63) / 64, Bb * Hh);
        attn_fused<<<grid, 256, ATTN_SMEM>>>();
    }
    {
        dim3 grid(Cc / 128, (M_TOT + 127) / 128);
        gemm_f16<1><<<grid, 256, GEMM_SMEM>>>(nullptr, proj_w, proj_b, nullptr, nullptr, out);
    }
}

// round 10
// speedup vs baseline: 5.4239x; 1.1548x over previous
#include <cuda_runtime.h>
#include <cuda_fp16.h>
#include <cstddef>
#include <cstdint>

// Problem constants
constexpr int Bb  = 64;
constexpr int Nn  = 197;
constexpr int Cc  = 768;
constexpr int Hh  = 12;
constexpr int Dd  = 64;
constexpr int M_TOT = Bb * Nn;        // 12608
constexpr int SLD  = 212;             // S row stride (floats): 208 cols + 4 pad

// Scratch (device globals) — fp16
__device__ __half g_q[(size_t)Bb * Hh * Nn * Dd];
__device__ __half g_k[(size_t)Bb * Hh * Nn * Dd];
__device__ __half g_v[(size_t)Bb * Hh * Nn * Dd];
__device__ float  g_rpb[(size_t)Hh * Nn * Nn];
__device__ __half g_o[(size_t)Bb * Nn * Cc];

// ---------------------------------------------------------------------------
// helpers
// ---------------------------------------------------------------------------
__device__ __forceinline__ unsigned pack2(float x, float y) {
    __half2 h = __float22half2_rn(make_float2(x, y));
    return *reinterpret_cast<unsigned*>(&h);
}

__device__ __forceinline__ void mma_f16(
    float& c0, float& c1, float& c2, float& c3,
    unsigned a0, unsigned a1, unsigned a2, unsigned a3,
    unsigned b0, unsigned b1)
{
    asm volatile(
        "mma.sync.aligned.m16n8k16.row.col.f32.f16.f16.f32 "
        "{%0,%1,%2,%3},{%4,%5,%6,%7},{%8,%9},{%0,%1,%2,%3};\n"
        : "+f"(c0), "+f"(c1), "+f"(c2), "+f"(c3)
        : "r"(a0), "r"(a1), "r"(a2), "r"(a3), "r"(b0), "r"(b1));
}

__device__ __forceinline__ void ldsm_x4(
    unsigned& r0, unsigned& r1, unsigned& r2, unsigned& r3, unsigned addr)
{
    asm volatile("ldmatrix.sync.aligned.m8n8.x4.shared.b16 {%0,%1,%2,%3}, [%4];"
                 : "=r"(r0), "=r"(r1), "=r"(r2), "=r"(r3) : "r"(addr));
}

__device__ __forceinline__ void ldsm_x4_trans(
    unsigned& r0, unsigned& r1, unsigned& r2, unsigned& r3, unsigned addr)
{
    asm volatile("ldmatrix.sync.aligned.m8n8.x4.trans.shared.b16 {%0,%1,%2,%3}, [%4];"
                 : "=r"(r0), "=r"(r1), "=r"(r2), "=r"(r3) : "r"(addr));
}

__device__ __forceinline__ void cp16(unsigned dst, const void* src) {
    asm volatile("cp.async.ca.shared.global [%0], [%1], 16;"
                 :: "r"(dst), "l"(src) : "memory");
}
__device__ __forceinline__ void cp_commit() {
    asm volatile("cp.async.commit_group;" ::: "memory");
}
__device__ __forceinline__ void cp_wait0() {
    asm volatile("cp.async.wait_group 0;" ::: "memory");
}

// ---------------------------------------------------------------------------
// Kernel 1: relative position bias gather
// ---------------------------------------------------------------------------
__global__ void rpb_kernel(const float* __restrict__ rel_table) {
    int tid = blockIdx.x * blockDim.x + threadIdx.x;
    const int total = Hh * Nn * Nn;
    if (tid >= total) return;
    int h = tid / (Nn * Nn);
    int r = tid % (Nn * Nn);
    int i = r / Nn, j = r % Nn;
    int idx;
    if (i == 0 && j == 0)      idx = 731;
    else if (i == 0)           idx = 729;
    else if (j == 0)           idx = 730;
    else {
        int a = i - 1, b = j - 1;
        int d0 = (a / 14 - b / 14) + 13;
        int d1 = (a % 14 - b % 14) + 13;
        idx = d0 * 27 + d1;
    }
    g_rpb[tid] = rel_table[idx * Hh + h];
}

// ---------------------------------------------------------------------------
// Kernels 2 & 4: fp16 GEMM  C = A @ W^T (+bias), ping-pong smem + ldmatrix
// (proven R6/R9 version, unchanged)
// ---------------------------------------------------------------------------
template <int EPI>
__global__ __launch_bounds__(256) void gemm_f16(
    const float* __restrict__ Af, const float* __restrict__ W,
    const float* __restrict__ b0v, const float* __restrict__ b1v,
    const float* __restrict__ b2v, float* __restrict__ out)
{
    constexpr int K = 768, BM = 128;
    constexpr int TSTR = 20;
    constexpr int BUFSZ = BM * TSTR;
    extern __shared__ unsigned gsm[];
    unsigned* Asb = gsm;
    unsigned* Bsb = gsm + 2 * BUFSZ;

    const unsigned as_base = (unsigned)__cvta_generic_to_shared(Asb);
    const unsigned bs_base = (unsigned)__cvta_generic_to_shared(Bsb);

    const __half* Ah = (const __half*)g_o;
    const int tid  = threadIdx.x;
    const int bm   = blockIdx.y * BM;
    const int bn   = blockIdx.x * BM;
    const int w    = tid >> 5, lane = tid & 31;
    const int wm   = w >> 1, wn = w & 1;
    const int m0w  = wm * 32, n0w = wn * 64;
    const int r    = lane >> 2, cg = lane & 3;

    const int a_row = (lane & 7) | (lane & 8);
    const int a_c4  = (lane & 16) >> 2;
    const int b_row = (lane & 7) | ((lane & 16) >> 1);
    const int b_c4  = (lane & 8) >> 1;

    float acc[2][8][4];
#pragma unroll
    for (int i = 0; i < 2; i++)
#pragma unroll
        for (int j = 0; j < 8; j++)
#pragma unroll
            for (int t = 0; t < 4; t++) acc[i][j][t] = 0.f;

    const int srow = tid >> 3;
    const int skc  = (tid & 7) * 4;

    uint2 sa2[4], sb2[4];
    auto loadA = [&](int i, int kbase) {
        int row = srow + i * 32;
        int gm = bm + row;
        if (EPI == 0) {
            float4 a = (gm < M_TOT)
                ? *(const float4*)(Af + (size_t)gm * K + kbase + skc)
                : make_float4(0, 0, 0, 0);
            sa2[i] = make_uint2(pack2(a.x, a.y), pack2(a.z, a.w));
        } else {
            sa2[i] = (gm < M_TOT)
                ? *(const uint2*)(Ah + (size_t)gm * K + kbase + skc)
                : make_uint2(0, 0);
        }
    };
    auto loadB = [&](int i, int kbase) {
        int row = srow + i * 32;
        float4 b = *(const float4*)(W + (size_t)(bn + row) * K + kbase + skc);
        sb2[i] = make_uint2(pack2(b.x, b.y), pack2(b.z, b.w));
    };

#pragma unroll
    for (int i = 0; i < 4; i++) { loadA(i, 0); loadB(i, 0); }
#pragma unroll
    for (int i = 0; i < 4; i++) {
        int row = srow + i * 32;
        *(uint2*)&Asb[row * TSTR + (skc >> 1)] = sa2[i];
        *(uint2*)&Bsb[row * TSTR + (skc >> 1)] = sb2[i];
    }
    __syncthreads();

    int buf = 0;
    for (int kc0 = 0; kc0 < K; kc0 += 32) {
        const bool more = (kc0 + 32) < K;
        if (more) {
#pragma unroll
            for (int i = 0; i < 4; i++) { loadA(i, kc0 + 32); loadB(i, kc0 + 32); }
        }

        const unsigned abuf = as_base + buf * BUFSZ * 4;
        const unsigned bbuf = bs_base + buf * BUFSZ * 4;
#pragma unroll
        for (int ks = 0; ks < 2; ks++) {
            const int kb = ks * 8;
            unsigned af[2][4], bf[8][2];
#pragma unroll
            for (int mt = 0; mt < 2; mt++) {
                unsigned aaddr = abuf +
                    ((m0w + mt * 16 + a_row) * TSTR + kb + a_c4) * 4;
                ldsm_x4(af[mt][0], af[mt][1], af[mt][2], af[mt][3], aaddr);
            }
#pragma unroll
            for (int j = 0; j < 8; j += 2) {
                unsigned baddr = bbuf +
                    ((n0w + j * 8 + b_row) * TSTR + kb + b_c4) * 4;
                ldsm_x4(bf[j][0], bf[j][1], bf[j + 1][0], bf[j + 1][1], baddr);
            }
#pragma unroll
            for (int mt = 0; mt < 2; mt++)
#pragma unroll
                for (int nt = 0; nt < 8; nt++)
                    mma_f16(acc[mt][nt][0], acc[mt][nt][1],
                            acc[mt][nt][2], acc[mt][nt][3],
                            af[mt][0], af[mt][1], af[mt][2], af[mt][3],
                            bf[nt][0], bf[nt][1]);
        }

        if (more) {
            unsigned* An = Asb + (buf ^ 1) * BUFSZ;
            unsigned* Bn = Bsb + (buf ^ 1) * BUFSZ;
#pragma unroll
            for (int i = 0; i < 4; i++) {
                int row = srow + i * 32;
                *(uint2*)&An[row * TSTR + (skc >> 1)] = sa2[i];
                *(uint2*)&Bn[row * TSTR + (skc >> 1)] = sb2[i];
            }
            __syncthreads();
            buf ^= 1;
        }
    }

#pragma unroll
    for (int mt = 0; mt < 2; mt++) {
        int mbase = bm + m0w + mt * 16;
#pragma unroll
        for (int nt = 0; nt < 8; nt++) {
            int nbase = bn + n0w + nt * 8 + 2 * cg;
#pragma unroll
            for (int half = 0; half < 2; half++) {
                int row = mbase + r + half * 8;
                if (row >= M_TOT) continue;
                float v0 = acc[mt][nt][half * 2 + 0];
                float v1 = acc[mt][nt][half * 2 + 1];
                if (EPI == 1) {
                    *(float2*)&out[(size_t)row * Cc + nbase] =
                        make_float2(v0 + b0v[nbase], v1 + b0v[nbase + 1]);
                } else {
                    int bI = row / Nn, n = row % Nn;
                    int which = nbase / Cc;
                    int cc = nbase % Cc;
                    int h = cc >> 6, d = cc & 63;
                    size_t off = (((size_t)bI * Hh + h) * Nn + n) * Dd + d;
                    if (which == 0)
                        *(unsigned*)&g_q[off] = pack2((v0 + b0v[cc]) * 0.125f,
                                                      (v1 + b0v[cc + 1]) * 0.125f);
                    else if (which == 1)
                        *(unsigned*)&g_k[off] = pack2(v0 + b1v[cc], v1 + b1v[cc + 1]);
                    else
                        *(unsigned*)&g_v[off] = pack2(v0 + b2v[cc], v1 + b2v[cc + 1]);
                }
            }
        }
    }
}

// ---------------------------------------------------------------------------
// Kernel 3: fused attention v3.
//  - scores: k-outer / n-inner, 4 n-tile accumulators live (A-frags loaded once)
//  - softmax: vectorized float2, register-resident single-pass
//  - V pad rows zeroed (R9 fix retained)
// 256 threads, 8 warps (2m x 4n). 3 syncthreads total.
// smem (u32): Qs[64][36] | Ks[256][36] (V overlays) | Ss[64][212] f32
// ---------------------------------------------------------------------------
__global__ __launch_bounds__(256, 2) void attn_fused() {
    extern __shared__ unsigned smemu[];
    unsigned* Qs = smemu;                       // [64][36]
    unsigned* Ks = smemu + 64 * 36;             // [256][36]; V overlays after scores
    float*    Ss = (float*)(smemu + 64 * 36 + 256 * 36);  // [64][212]

    const unsigned qs_base = (unsigned)__cvta_generic_to_shared(Qs);
    const unsigned ks_base = (unsigned)__cvta_generic_to_shared(Ks);
    const unsigned ss_base = (unsigned)__cvta_generic_to_shared(Ss);

    const int bh = blockIdx.y, h = bh % Hh, bI = bh / Hh;
    const int m0 = blockIdx.x * 64;
    const int tid = threadIdx.x, lane = tid & 31, w = tid >> 5;
    const int wm = w >> 2;          // 0..1 : 32 m-rows
    const int wn = w & 3;           // 0..3 : 16 n-cols
    const int r = lane >> 2, cg = lane & 3;
    const __half* qb = g_q + (size_t)bh * Nn * Dd;
    const __half* kb = g_k + (size_t)bh * Nn * Dd;
    const __half* vb = g_v + (size_t)bh * Nn * Dd;

    const int a_row = (lane & 7) | (lane & 8);
    const int a_c4  = (lane & 16) >> 2;
    const int b_row = (lane & 7) | ((lane & 16) >> 1);
    const int b_c4  = (lane & 8) >> 1;

    // ---- stage Q (64 rows) + K (197 rows) via cp.async ----
    for (int s = tid; s < 64 * 8; s += 256) {
        int row = s >> 3, c4 = s & 7;
        if (m0 + row < Nn)
            cp16(qs_base + (row * 36 + c4 * 4) * 4,
                 qb + (size_t)(m0 + row) * Dd + c4 * 8);
    }
    for (int s = tid; s < 197 * 8; s += 256) {
        int row = s >> 3, c4 = s & 7;
        cp16(ks_base + (row * 36 + c4 * 4) * 4,
             kb + (size_t)row * Dd + c4 * 8);
    }
    cp_commit();
    cp_wait0();
    __syncthreads();

    // ---- scores: k-outer, 4 n-tile accumulators live ----
    {
        float acc[4][2][2][4];          // [n-tile][mt][nt2][frag]
#pragma unroll
        for (int a = 0; a < 4; a++)
#pragma unroll
            for (int i = 0; i < 2; i++)
#pragma unroll
                for (int j = 0; j < 2; j++)
#pragma unroll
                    for (int t = 0; t < 4; t++) acc[a][i][j][t] = 0.f;

#pragma unroll
        for (int ks = 0; ks < 4; ks++) {
            const int kbu = ks * 8;
            unsigned af[2][4];
#pragma unroll
            for (int mt = 0; mt < 2; mt++) {
                unsigned aaddr = qs_base +
                    ((wm * 32 + mt * 16 + a_row) * 36 + kbu + a_c4) * 4;
                ldsm_x4(af[mt][0], af[mt][1], af[mt][2], af[mt][3], aaddr);
            }
#pragma unroll
            for (int nt0 = 0; nt0 < 4; nt0++) {
                unsigned bf[2][2];
                unsigned baddr = ks_base +
                    ((nt0 * 64 + wn * 16 + b_row) * 36 + kbu + b_c4) * 4;
                ldsm_x4(bf[0][0], bf[0][1], bf[1][0], bf[1][1], baddr);
#pragma unroll
                for (int mt = 0; mt < 2; mt++)
#pragma unroll
                    for (int nt = 0; nt < 2; nt++)
                        mma_f16(acc[nt0][mt][nt][0], acc[nt0][mt][nt][1],
                                acc[nt0][mt][nt][2], acc[nt0][mt][nt][3],
                                af[mt][0], af[mt][1], af[mt][2], af[mt][3],
                                bf[nt][0], bf[nt][1]);
            }
        }

        // write all S tiles (+rpb); cols >= 208 skipped; invalid cells -> 0
#pragma unroll
        for (int nt0 = 0; nt0 < 4; nt0++) {
            const int n0 = nt0 * 64;
#pragma unroll
            for (int mt = 0; mt < 2; mt++) {
                int mlb = wm * 32 + mt * 16;
#pragma unroll
                for (int nt = 0; nt < 2; nt++) {
                    int nl = wn * 16 + nt * 8 + 2 * cg;
                    if (n0 + nl >= 208) continue;
#pragma unroll
                    for (int half = 0; half < 2; half++) {
                        int ml = mlb + r + half * 8;
                        int mg = m0 + ml;
                        float v0 = 0.f, v1 = 0.f;
                        if (mg < Nn) {
                            int ng0 = n0 + nl, ng1 = ng0 + 1;
                            const float* rp = g_rpb + ((size_t)h * Nn + mg) * Nn;
                            if (ng0 < Nn) v0 = acc[nt0][mt][nt][half * 2 + 0] + rp[ng0];
                            if (ng1 < Nn) v1 = acc[nt0][mt][nt][half * 2 + 1] + rp[ng1];
                        }
                        *(float2*)&Ss[ml * SLD + n0 + nl] = make_float2(v0, v1);
                    }
                }
            }
        }
    }
    __syncthreads();   // scores done (Ks reads finished), S fully written

    // ---- stage V into Ks region (overlaps with softmax) ----
    // Rows 197..207 are read by PV ldsm.trans (13 k-steps -> tokens 0..207):
    // they must be zero, else garbage fp16 poisons the accumulator (R8 bug).
    for (int s = tid; s < 208 * 8; s += 256) {
        int row = s >> 3, c4 = s & 7;
        if (row < Nn)
            cp16(ks_base + (row * 36 + c4 * 4) * 4,
                 vb + (size_t)row * Dd + c4 * 8);
        else
            *(uint4*)&Ks[row * 36 + c4 * 4] = make_uint4(0, 0, 0, 0);
    }
    cp_commit();

    // ---- softmax: vectorized float2, register-resident; pack to half2 ----
    for (int row = w; row < 64; row += 8) {
        float* sr = Ss + row * SLD;
        float2 v[4];
        float mx = -1e30f;
#pragma unroll
        for (int i = 0; i < 4; i++) {
            int j = lane + 32 * i;                 // pair index (cols 2j, 2j+1)
            v[i] = (j < 104) ? *(float2*)&sr[2 * j] : make_float2(0.f, 0.f);
            if (2 * j < Nn)     mx = fmaxf(mx, v[i].x);
            if (2 * j + 1 < Nn) mx = fmaxf(mx, v[i].y);
        }
#pragma unroll
        for (int o = 16; o; o >>= 1) mx = fmaxf(mx, __shfl_xor_sync(0xffffffffu, mx, o));
        float s = 0.f;
#pragma unroll
        for (int i = 0; i < 4; i++) {
            int j = lane + 32 * i;
            float e0 = (2 * j < Nn)     ? __expf(v[i].x - mx) : 0.f;
            float e1 = (2 * j + 1 < Nn) ? __expf(v[i].y - mx) : 0.f;
            v[i].x = e0; v[i].y = e1;
            s += e0 + e1;
        }
#pragma unroll
        for (int o = 16; o; o >>= 1) s += __shfl_xor_sync(0xffffffffu, s, o);
        float inv = 1.f / s;
        unsigned* pu = (unsigned*)sr;
#pragma unroll
        for (int i = 0; i < 4; i++) {
            int j = lane + 32 * i;
            if (j < 104) pu[j] = pack2(v[i].x * inv, v[i].y * inv);
        }
    }

    cp_wait0();
    __syncthreads();   // V visible to all; probs packed

    // ---- PV: 13 k16-steps over tokens 0..207; V consumed via ldsm.trans ----
    float accO[2][2][4];
#pragma unroll
    for (int i = 0; i < 2; i++)
#pragma unroll
        for (int j = 0; j < 2; j++)
#pragma unroll
            for (int t = 0; t < 4; t++) accO[i][j][t] = 0.f;

#pragma unroll
    for (int kst = 0; kst < 13; kst++) {
        const int kbu = kst * 8;                  // u32 offset in packed P row
        unsigned af[2][4], bf[2][2];
#pragma unroll
        for (int mt = 0; mt < 2; mt++) {
            unsigned aaddr = ss_base +
                ((wm * 32 + mt * 16 + a_row) * SLD + kbu + a_c4) * 4;
            ldsm_x4(af[mt][0], af[mt][1], af[mt][2], af[mt][3], aaddr);
        }
        {
            // trans ldsm: rows = tokens, cols = head dims -> B-frag (k=tok, n=d)
            unsigned vaddr = ks_base +
                (((kst * 16 + (lane & 15)) * 36) + wn * 8 + ((lane >> 4) * 4)) * 4;
            ldsm_x4_trans(bf[0][0], bf[0][1], bf[1][0], bf[1][1], vaddr);
        }
#pragma unroll
        for (int mt = 0; mt < 2; mt++)
#pragma unroll
            for (int nt = 0; nt < 2; nt++)
                mma_f16(accO[mt][nt][0], accO[mt][nt][1],
                        accO[mt][nt][2], accO[mt][nt][3],
                        af[mt][0], af[mt][1], af[mt][2], af[mt][3],
                        bf[nt][0], bf[nt][1]);
    }

    // ---- store O tile (fp16) ----
#pragma unroll
    for (int mt = 0; mt < 2; mt++) {
        int mbase = m0 + wm * 32 + mt * 16;
#pragma unroll
        for (int nt = 0; nt < 2; nt++) {
            int nb = wn * 16 + nt * 8 + 2 * cg;
#pragma unroll
            for (int half = 0; half < 2; half++) {
                int m = mbase + r + half * 8;
                if (m >= Nn) continue;
                size_t o = ((size_t)bI * Nn + m) * Cc + h * Dd + nb;
                *(unsigned*)&g_o[o] = pack2(accO[mt][nt][half * 2 + 0],
                                            accO[mt][nt][half * 2 + 1]);
            }
        }
    }
}

// ---------------------------------------------------------------------------
extern "C" void kernel_launch(void* const* d_in, const int* in_sizes, int n_in,
                              void* d_out, int out_size)
{
    const float* x         = (const float*)d_in[0];
    const float* qkv_w     = (const float*)d_in[1];
    const float* q_bias    = (const float*)d_in[2];
    const float* k_bias    = (const float*)d_in[3];
    const float* v_bias    = (const float*)d_in[4];
    const float* rel_table = (const float*)d_in[5];
    const float* proj_w    = (const float*)d_in[6];
    const float* proj_b    = (const float*)d_in[7];
    float* out = (float*)d_out;

    constexpr int GEMM_SMEM = 4 * 128 * 20 * 4;                       // 40960
    constexpr int ATTN_SMEM = (64 * 36 + 256 * 36 + 64 * SLD) * 4;    // 100352

    static bool attr_done = false;
    if (!attr_done) {
        cudaFuncSetAttribute(gemm_f16<0>, cudaFuncAttributeMaxDynamicSharedMemorySize, GEMM_SMEM);
        cudaFuncSetAttribute(gemm_f16<1>, cudaFuncAttributeMaxDynamicSharedMemorySize, GEMM_SMEM);
        cudaFuncSetAttribute(attn_fused,  cudaFuncAttributeMaxDynamicSharedMemorySize, ATTN_SMEM);
        attr_done = true;
    }

    {
        int total = Hh * Nn * Nn;
        rpb_kernel<<<(total + 255) / 256, 256>>>(rel_table);
    }
    {
        dim3 grid(3 * Cc / 128, (M_TOT + 127) / 128);
        gemm_f16<0><<<grid, 256, GEMM_SMEM>>>(x, qkv_w, q_bias, k_bias, v_bias, nullptr);
    }
    {
        dim3 grid((Nn + 63) / 64, Bb * Hh);
        attn_fused<<<grid, 256, ATTN_SMEM>>>();
    }
    {
        dim3 grid(Cc / 128, (M_TOT + 127) / 128);
        gemm_f16<1><<<grid, 256, GEMM_SMEM>>>(nullptr, proj_w, proj_b, nullptr, nullptr, out);
    }
}

// round 12
// speedup vs baseline: 5.8089x; 1.0710x over previous
#include <cuda_runtime.h>
#include <cuda_fp16.h>
#include <cstddef>
#include <cstdint>

// Problem constants
constexpr int Bb  = 64;
constexpr int Nn  = 197;
constexpr int Cc  = 768;
constexpr int Hh  = 12;
constexpr int Dd  = 64;
constexpr int M_TOT = Bb * Nn;        // 12608
constexpr int SLD  = 212;             // S row stride (floats): 208 cols + 4 pad

// Scratch (device globals) — fp16
__device__ __half g_q[(size_t)Bb * Hh * Nn * Dd];
__device__ __half g_k[(size_t)Bb * Hh * Nn * Dd];
__device__ __half g_v[(size_t)Bb * Hh * Nn * Dd];
__device__ float  g_rpb[(size_t)Hh * Nn * Nn];
__device__ __half g_o[(size_t)Bb * Nn * Cc];
// pre-converted fp16 inputs
__device__ __half g_xh[(size_t)M_TOT * Cc];          // x
__device__ __half g_wh[(size_t)3 * Cc * Cc];         // qkv_w
__device__ __half g_pwh[(size_t)Cc * Cc];            // proj_w

// ---------------------------------------------------------------------------
// helpers
// ---------------------------------------------------------------------------
__device__ __forceinline__ unsigned pack2(float x, float y) {
    __half2 h = __float22half2_rn(make_float2(x, y));
    return *reinterpret_cast<unsigned*>(&h);
}

__device__ __forceinline__ void mma_f16(
    float& c0, float& c1, float& c2, float& c3,
    unsigned a0, unsigned a1, unsigned a2, unsigned a3,
    unsigned b0, unsigned b1)
{
    asm volatile(
        "mma.sync.aligned.m16n8k16.row.col.f32.f16.f16.f32 "
        "{%0,%1,%2,%3},{%4,%5,%6,%7},{%8,%9},{%0,%1,%2,%3};\n"
        : "+f"(c0), "+f"(c1), "+f"(c2), "+f"(c3)
        : "r"(a0), "r"(a1), "r"(a2), "r"(a3), "r"(b0), "r"(b1));
}

__device__ __forceinline__ void ldsm_x4(
    unsigned& r0, unsigned& r1, unsigned& r2, unsigned& r3, unsigned addr)
{
    asm volatile("ldmatrix.sync.aligned.m8n8.x4.shared.b16 {%0,%1,%2,%3}, [%4];"
                 : "=r"(r0), "=r"(r1), "=r"(r2), "=r"(r3) : "r"(addr));
}

__device__ __forceinline__ void ldsm_x4_trans(
    unsigned& r0, unsigned& r1, unsigned& r2, unsigned& r3, unsigned addr)
{
    asm volatile("ldmatrix.sync.aligned.m8n8.x4.trans.shared.b16 {%0,%1,%2,%3}, [%4];"
                 : "=r"(r0), "=r"(r1), "=r"(r2), "=r"(r3) : "r"(addr));
}

__device__ __forceinline__ void cp16(unsigned dst, const void* src) {
    asm volatile("cp.async.ca.shared.global [%0], [%1], 16;"
                 :: "r"(dst), "l"(src) : "memory");
}
// predicated: bytes==0 -> zero-fill destination
__device__ __forceinline__ void cp16p(unsigned dst, const void* src, unsigned bytes) {
    asm volatile("cp.async.ca.shared.global [%0], [%1], 16, %2;"
                 :: "r"(dst), "l"(src), "r"(bytes) : "memory");
}
__device__ __forceinline__ void cp_commit() {
    asm volatile("cp.async.commit_group;" ::: "memory");
}
template <int N>
__device__ __forceinline__ void cp_wait() {
    asm volatile("cp.async.wait_group %0;" :: "n"(N) : "memory");
}

// ---------------------------------------------------------------------------
// Kernel 0: fp32 -> fp16 conversion (x, qkv_w, proj_w)
// ---------------------------------------------------------------------------
__global__ void cvt_kernel(const float* __restrict__ src, __half* __restrict__ dst,
                           int n4) {
    int i = blockIdx.x * blockDim.x + threadIdx.x;
    if (i >= n4) return;
    float4 f = ((const float4*)src)[i];
    ((uint2*)dst)[i] = make_uint2(pack2(f.x, f.y), pack2(f.z, f.w));
}

// ---------------------------------------------------------------------------
// Kernel 1: relative position bias gather
// ---------------------------------------------------------------------------
__global__ void rpb_kernel(const float* __restrict__ rel_table) {
    int tid = blockIdx.x * blockDim.x + threadIdx.x;
    const int total = Hh * Nn * Nn;
    if (tid >= total) return;
    int h = tid / (Nn * Nn);
    int r = tid % (Nn * Nn);
    int i = r / Nn, j = r % Nn;
    int idx;
    if (i == 0 && j == 0)      idx = 731;
    else if (i == 0)           idx = 729;
    else if (j == 0)           idx = 730;
    else {
        int a = i - 1, b = j - 1;
        int d0 = (a / 14 - b / 14) + 13;
        int d1 = (a % 14 - b % 14) + 13;
        idx = d0 * 27 + d1;
    }
    g_rpb[tid] = rel_table[idx * Hh + h];
}

// ---------------------------------------------------------------------------
// Kernels 2 & 4: fp16 GEMM  C = A @ W^T (+bias)
// 3-stage cp.async pipeline, ldmatrix fragments, fp16 A and W (pre-converted).
// BM=128 BN=128 KC=32, 256 threads, 8 warps (4m x 2n), warp 32x64.
// smem: As[3][128][20] | Bs[3][128][20] u32 = 61440 B
// EPI==0: scatter q/k/v (q pre-scaled).  EPI==1: out = A@W^T + proj_b (fp32)
// ---------------------------------------------------------------------------
template <int EPI>
__global__ __launch_bounds__(256, 2) void gemm_f16(
    const __half* __restrict__ A, const __half* __restrict__ W,
    const float* __restrict__ b0v, const float* __restrict__ b1v,
    const float* __restrict__ b2v, float* __restrict__ out)
{
    constexpr int K = 768, KC = 32, NCHUNK = K / KC;   // 24
    constexpr int TSTR = 20;                           // u32 per row
    constexpr int STG = 128 * TSTR;                    // 2560 u32 per matrix stage
    extern __shared__ unsigned gsm[];
    const unsigned as_base = (unsigned)__cvta_generic_to_shared(gsm);
    const unsigned bs_base = as_base + 3 * STG * 4;

    const int tid  = threadIdx.x;
    const int bm   = blockIdx.y * 128;
    const int bn   = blockIdx.x * 128;
    const int w    = tid >> 5, lane = tid & 31;
    const int wm   = w >> 1, wn = w & 1;
    const int m0w  = wm * 32, n0w = wn * 64;
    const int r    = lane >> 2, cg = lane & 3;

    const int a_row = (lane & 7) | (lane & 8);
    const int a_c4  = (lane & 16) >> 2;
    const int b_row = (lane & 7) | ((lane & 16) >> 1);
    const int b_c4  = (lane & 8) >> 1;

    // staging decomposition: 512 16B-chunks per matrix per stage, 2 per thread
    const int srow0 = tid >> 2;            // rows tid>>2 and (tid>>2)+64
    const int sch   = tid & 3;             // 16B chunk within row (8 fp16)

    auto issue = [&](int chunk) {
        const int kc0 = chunk * KC;
        const unsigned ab = as_base + (chunk % 3) * STG * 4;
        const unsigned bb = bs_base + (chunk % 3) * STG * 4;
#pragma unroll
        for (int i = 0; i < 2; i++) {
            int row = srow0 + i * 64;
            int gm = bm + row;
            cp16p(ab + (row * TSTR + sch * 4) * 4,
                  A + (size_t)gm * K + kc0 + sch * 8,
                  (gm < M_TOT) ? 16u : 0u);
            cp16(bb + (row * TSTR + sch * 4) * 4,
                 W + (size_t)(bn + row) * K + kc0 + sch * 8);
        }
        cp_commit();
    };

    float acc[2][8][4];
#pragma unroll
    for (int i = 0; i < 2; i++)
#pragma unroll
        for (int j = 0; j < 8; j++)
#pragma unroll
            for (int t = 0; t < 4; t++) acc[i][j][t] = 0.f;

    issue(0);
    issue(1);

    for (int c = 0; c < NCHUNK; c++) {
        if (c + 1 < NCHUNK) cp_wait<1>(); else cp_wait<0>();
        __syncthreads();
        if (c + 2 < NCHUNK) issue(c + 2);

        const unsigned abuf = as_base + (c % 3) * STG * 4;
        const unsigned bbuf = bs_base + (c % 3) * STG * 4;
#pragma unroll
        for (int ks = 0; ks < 2; ks++) {
            const int kb = ks * 8;
            unsigned af[2][4], bf[8][2];
#pragma unroll
            for (int mt = 0; mt < 2; mt++) {
                unsigned aaddr = abuf +
                    ((m0w + mt * 16 + a_row) * TSTR + kb + a_c4) * 4;
                ldsm_x4(af[mt][0], af[mt][1], af[mt][2], af[mt][3], aaddr);
            }
#pragma unroll
            for (int j = 0; j < 8; j += 2) {
                unsigned baddr = bbuf +
                    ((n0w + j * 8 + b_row) * TSTR + kb + b_c4) * 4;
                ldsm_x4(bf[j][0], bf[j][1], bf[j + 1][0], bf[j + 1][1], baddr);
            }
#pragma unroll
            for (int mt = 0; mt < 2; mt++)
#pragma unroll
                for (int nt = 0; nt < 8; nt++)
                    mma_f16(acc[mt][nt][0], acc[mt][nt][1],
                            acc[mt][nt][2], acc[mt][nt][3],
                            af[mt][0], af[mt][1], af[mt][2], af[mt][3],
                            bf[nt][0], bf[nt][1]);
        }
        __syncthreads();   // all warps done with stage c before it is reissued
    }

    // Epilogue
#pragma unroll
    for (int mt = 0; mt < 2; mt++) {
        int mbase = bm + m0w + mt * 16;
#pragma unroll
        for (int nt = 0; nt < 8; nt++) {
            int nbase = bn + n0w + nt * 8 + 2 * cg;
#pragma unroll
            for (int half = 0; half < 2; half++) {
                int row = mbase + r + half * 8;
                if (row >= M_TOT) continue;
                float v0 = acc[mt][nt][half * 2 + 0];
                float v1 = acc[mt][nt][half * 2 + 1];
                if (EPI == 1) {
                    *(float2*)&out[(size_t)row * Cc + nbase] =
                        make_float2(v0 + b0v[nbase], v1 + b0v[nbase + 1]);
                } else {
                    int bI = row / Nn, n = row % Nn;
                    int which = nbase / Cc;
                    int cc = nbase % Cc;
                    int h = cc >> 6, d = cc & 63;
                    size_t off = (((size_t)bI * Hh + h) * Nn + n) * Dd + d;
                    if (which == 0)
                        *(unsigned*)&g_q[off] = pack2((v0 + b0v[cc]) * 0.125f,
                                                      (v1 + b0v[cc + 1]) * 0.125f);
                    else if (which == 1)
                        *(unsigned*)&g_k[off] = pack2(v0 + b1v[cc], v1 + b1v[cc + 1]);
                    else
                        *(unsigned*)&g_v[off] = pack2(v0 + b2v[cc], v1 + b2v[cc + 1]);
                }
            }
        }
    }
}

// ---------------------------------------------------------------------------
// Kernel 3: fused attention v3 (unchanged from R10)
// ---------------------------------------------------------------------------
__global__ __launch_bounds__(256, 2) void attn_fused() {
    extern __shared__ unsigned smemu[];
    unsigned* Qs = smemu;                       // [64][36]
    unsigned* Ks = smemu + 64 * 36;             // [256][36]; V overlays after scores
    float*    Ss = (float*)(smemu + 64 * 36 + 256 * 36);  // [64][212]

    const unsigned qs_base = (unsigned)__cvta_generic_to_shared(Qs);
    const unsigned ks_base = (unsigned)__cvta_generic_to_shared(Ks);
    const unsigned ss_base = (unsigned)__cvta_generic_to_shared(Ss);

    const int bh = blockIdx.y, h = bh % Hh, bI = bh / Hh;
    const int m0 = blockIdx.x * 64;
    const int tid = threadIdx.x, lane = tid & 31, w = tid >> 5;
    const int wm = w >> 2;
    const int wn = w & 3;
    const int r = lane >> 2, cg = lane & 3;
    const __half* qb = g_q + (size_t)bh * Nn * Dd;
    const __half* kb = g_k + (size_t)bh * Nn * Dd;
    const __half* vb = g_v + (size_t)bh * Nn * Dd;

    const int a_row = (lane & 7) | (lane & 8);
    const int a_c4  = (lane & 16) >> 2;
    const int b_row = (lane & 7) | ((lane & 16) >> 1);
    const int b_c4  = (lane & 8) >> 1;

    for (int s = tid; s < 64 * 8; s += 256) {
        int row = s >> 3, c4 = s & 7;
        if (m0 + row < Nn)
            cp16(qs_base + (row * 36 + c4 * 4) * 4,
                 qb + (size_t)(m0 + row) * Dd + c4 * 8);
    }
    for (int s = tid; s < 197 * 8; s += 256) {
        int row = s >> 3, c4 = s & 7;
        cp16(ks_base + (row * 36 + c4 * 4) * 4,
             kb + (size_t)row * Dd + c4 * 8);
    }
    cp_commit();
    cp_wait<0>();
    __syncthreads();

    // ---- scores: k-outer, 4 n-tile accumulators live ----
    {
        float acc[4][2][2][4];
#pragma unroll
        for (int a = 0; a < 4; a++)
#pragma unroll
            for (int i = 0; i < 2; i++)
#pragma unroll
                for (int j = 0; j < 2; j++)
#pragma unroll
                    for (int t = 0; t < 4; t++) acc[a][i][j][t] = 0.f;

#pragma unroll
        for (int ks = 0; ks < 4; ks++) {
            const int kbu = ks * 8;
            unsigned af[2][4];
#pragma unroll
            for (int mt = 0; mt < 2; mt++) {
                unsigned aaddr = qs_base +
                    ((wm * 32 + mt * 16 + a_row) * 36 + kbu + a_c4) * 4;
                ldsm_x4(af[mt][0], af[mt][1], af[mt][2], af[mt][3], aaddr);
            }
#pragma unroll
            for (int nt0 = 0; nt0 < 4; nt0++) {
                unsigned bf[2][2];
                unsigned baddr = ks_base +
                    ((nt0 * 64 + wn * 16 + b_row) * 36 + kbu + b_c4) * 4;
                ldsm_x4(bf[0][0], bf[0][1], bf[1][0], bf[1][1], baddr);
#pragma unroll
                for (int mt = 0; mt < 2; mt++)
#pragma unroll
                    for (int nt = 0; nt < 2; nt++)
                        mma_f16(acc[nt0][mt][nt][0], acc[nt0][mt][nt][1],
                                acc[nt0][mt][nt][2], acc[nt0][mt][nt][3],
                                af[mt][0], af[mt][1], af[mt][2], af[mt][3],
                                bf[nt][0], bf[nt][1]);
            }
        }

#pragma unroll
        for (int nt0 = 0; nt0 < 4; nt0++) {
            const int n0 = nt0 * 64;
#pragma unroll
            for (int mt = 0; mt < 2; mt++) {
                int mlb = wm * 32 + mt * 16;
#pragma unroll
                for (int nt = 0; nt < 2; nt++) {
                    int nl = wn * 16 + nt * 8 + 2 * cg;
                    if (n0 + nl >= 208) continue;
#pragma unroll
                    for (int half = 0; half < 2; half++) {
                        int ml = mlb + r + half * 8;
                        int mg = m0 + ml;
                        float v0 = 0.f, v1 = 0.f;
                        if (mg < Nn) {
                            int ng0 = n0 + nl, ng1 = ng0 + 1;
                            const float* rp = g_rpb + ((size_t)h * Nn + mg) * Nn;
                            if (ng0 < Nn) v0 = acc[nt0][mt][nt][half * 2 + 0] + rp[ng0];
                            if (ng1 < Nn) v1 = acc[nt0][mt][nt][half * 2 + 1] + rp[ng1];
                        }
                        *(float2*)&Ss[ml * SLD + n0 + nl] = make_float2(v0, v1);
                    }
                }
            }
        }
    }
    __syncthreads();

    // ---- stage V (rows >= 197 zeroed — required for PV k-coverage 0..207) ----
    for (int s = tid; s < 208 * 8; s += 256) {
        int row = s >> 3, c4 = s & 7;
        if (row < Nn)
            cp16(ks_base + (row * 36 + c4 * 4) * 4,
                 vb + (size_t)row * Dd + c4 * 8);
        else
            *(uint4*)&Ks[row * 36 + c4 * 4] = make_uint4(0, 0, 0, 0);
    }
    cp_commit();

    // ---- softmax: vectorized float2, register-resident; pack to half2 ----
    for (int row = w; row < 64; row += 8) {
        float* sr = Ss + row * SLD;
        float2 v[4];
        float mx = -1e30f;
#pragma unroll
        for (int i = 0; i < 4; i++) {
            int j = lane + 32 * i;
            v[i] = (j < 104) ? *(float2*)&sr[2 * j] : make_float2(0.f, 0.f);
            if (2 * j < Nn)     mx = fmaxf(mx, v[i].x);
            if (2 * j + 1 < Nn) mx = fmaxf(mx, v[i].y);
        }
#pragma unroll
        for (int o = 16; o; o >>= 1) mx = fmaxf(mx, __shfl_xor_sync(0xffffffffu, mx, o));
        float s = 0.f;
#pragma unroll
        for (int i = 0; i < 4; i++) {
            int j = lane + 32 * i;
            float e0 = (2 * j < Nn)     ? __expf(v[i].x - mx) : 0.f;
            float e1 = (2 * j + 1 < Nn) ? __expf(v[i].y - mx) : 0.f;
            v[i].x = e0; v[i].y = e1;
            s += e0 + e1;
        }
#pragma unroll
        for (int o = 16; o; o >>= 1) s += __shfl_xor_sync(0xffffffffu, s, o);
        float inv = 1.f / s;
        unsigned* pu = (unsigned*)sr;
#pragma unroll
        for (int i = 0; i < 4; i++) {
            int j = lane + 32 * i;
            if (j < 104) pu[j] = pack2(v[i].x * inv, v[i].y * inv);
        }
    }

    cp_wait<0>();
    __syncthreads();

    // ---- PV: 13 k16-steps; V consumed via ldsm.trans ----
    float accO[2][2][4];
#pragma unroll
    for (int i = 0; i < 2; i++)
#pragma unroll
        for (int j = 0; j < 2; j++)
#pragma unroll
            for (int t = 0; t < 4; t++) accO[i][j][t] = 0.f;

#pragma unroll
    for (int kst = 0; kst < 13; kst++) {
        const int kbu = kst * 8;
        unsigned af[2][4], bf[2][2];
#pragma unroll
        for (int mt = 0; mt < 2; mt++) {
            unsigned aaddr = ss_base +
                ((wm * 32 + mt * 16 + a_row) * SLD + kbu + a_c4) * 4;
            ldsm_x4(af[mt][0], af[mt][1], af[mt][2], af[mt][3], aaddr);
        }
        {
            unsigned vaddr = ks_base +
                (((kst * 16 + (lane & 15)) * 36) + wn * 8 + ((lane >> 4) * 4)) * 4;
            ldsm_x4_trans(bf[0][0], bf[0][1], bf[1][0], bf[1][1], vaddr);
        }
#pragma unroll
        for (int mt = 0; mt < 2; mt++)
#pragma unroll
            for (int nt = 0; nt < 2; nt++)
                mma_f16(accO[mt][nt][0], accO[mt][nt][1],
                        accO[mt][nt][2], accO[mt][nt][3],
                        af[mt][0], af[mt][1], af[mt][2], af[mt][3],
                        bf[nt][0], bf[nt][1]);
    }

#pragma unroll
    for (int mt = 0; mt < 2; mt++) {
        int mbase = m0 + wm * 32 + mt * 16;
#pragma unroll
        for (int nt = 0; nt < 2; nt++) {
            int nb = wn * 16 + nt * 8 + 2 * cg;
#pragma unroll
            for (int half = 0; half < 2; half++) {
                int m = mbase + r + half * 8;
                if (m >= Nn) continue;
                size_t o = ((size_t)bI * Nn + m) * Cc + h * Dd + nb;
                *(unsigned*)&g_o[o] = pack2(accO[mt][nt][half * 2 + 0],
                                            accO[mt][nt][half * 2 + 1]);
            }
        }
    }
}

// ---------------------------------------------------------------------------
extern "C" void kernel_launch(void* const* d_in, const int* in_sizes, int n_in,
                              void* d_out, int out_size)
{
    const float* x         = (const float*)d_in[0];
    const float* qkv_w     = (const float*)d_in[1];
    const float* q_bias    = (const float*)d_in[2];
    const float* k_bias    = (const float*)d_in[3];
    const float* v_bias    = (const float*)d_in[4];
    const float* rel_table = (const float*)d_in[5];
    const float* proj_w    = (const float*)d_in[6];
    const float* proj_b    = (const float*)d_in[7];
    float* out = (float*)d_out;

    constexpr int GEMM_SMEM = 6 * 128 * 20 * 4;                       // 61440
    constexpr int ATTN_SMEM = (64 * 36 + 256 * 36 + 64 * SLD) * 4;    // 100352

    static bool attr_done = false;
    if (!attr_done) {
        cudaFuncSetAttribute(gemm_f16<0>, cudaFuncAttributeMaxDynamicSharedMemorySize, GEMM_SMEM);
        cudaFuncSetAttribute(gemm_f16<1>, cudaFuncAttributeMaxDynamicSharedMemorySize, GEMM_SMEM);
        cudaFuncSetAttribute(attn_fused,  cudaFuncAttributeMaxDynamicSharedMemorySize, ATTN_SMEM);
        attr_done = true;
    }

    // Resolve DEVICE addresses of __device__ symbols (host-side &symbol is
    // invalid — that was the R11 bug: g_o was passed as a raw symbol).
    __half *d_xh, *d_wh, *d_pwh, *d_o;
    cudaGetSymbolAddress((void**)&d_xh,  g_xh);
    cudaGetSymbolAddress((void**)&d_wh,  g_wh);
    cudaGetSymbolAddress((void**)&d_pwh, g_pwh);
    cudaGetSymbolAddress((void**)&d_o,   g_o);

    // 0. fp32 -> fp16 conversions
    {
        int n4x = M_TOT * Cc / 4;        // 2420736
        cvt_kernel<<<(n4x + 255) / 256, 256>>>(x, d_xh, n4x);
        int n4w = 3 * Cc * Cc / 4;       // 442368
        cvt_kernel<<<(n4w + 255) / 256, 256>>>(qkv_w, d_wh, n4w);
        int n4p = Cc * Cc / 4;           // 147456
        cvt_kernel<<<(n4p + 255) / 256, 256>>>(proj_w, d_pwh, n4p);
    }
    // 1. relative position bias gather
    {
        int total = Hh * Nn * Nn;
        rpb_kernel<<<(total + 255) / 256, 256>>>(rel_table);
    }
    // 2. QKV projection + scatter
    {
        dim3 grid(3 * Cc / 128, (M_TOT + 127) / 128);
        gemm_f16<0><<<grid, 256, GEMM_SMEM>>>(d_xh, d_wh, q_bias, k_bias, v_bias, nullptr);
    }
    // 3. fused attention
    {
        dim3 grid((Nn + 63) / 64, Bb * Hh);
        attn_fused<<<grid, 256, ATTN_SMEM>>>();
    }
    // 4. output projection
    {
        dim3 grid(Cc / 128, (M_TOT + 127) / 128);
        gemm_f16<1><<<grid, 256, GEMM_SMEM>>>(d_o, d_pwh, proj_b,
                                              nullptr, nullptr, out);
    }
}